// round 4
// baseline (speedup 1.0000x reference)
#include <cuda_runtime.h>
#include <cstdint>

#define B_  32
#define T_  512
#define H_  1024
#define G4_ 4096
#define M_  (B_ * T_)   // 16384
#define NBLK 128
#define NTHR 512

// ---------------- static device scratch (no allocations allowed) ----------------
__device__ float g_xg[(size_t)M_ * G4_];     // gate preactivations for current layer
__device__ float g_h0seq[(size_t)M_ * H_];   // layer-0 output sequence (normal layout)
// frag-permuted recurrent h, double buffered: [buf][s(128)][mt(2)][lane(32)][r(4)]
__device__ float g_hA[2][32768];
// per-producer dataflow flags: [buf][block*8] (32B padded), monotonic write counters
__device__ unsigned g_flag[2][NBLK * 8];

// ---------------- helpers ----------------
__device__ __forceinline__ float f2tf32(float x) {
    uint32_t r;
    asm("cvt.rna.tf32.f32 %0, %1;" : "=r"(r) : "f"(x));
    return __uint_as_float(r);
}

__device__ __forceinline__ void mma_tf32(float& c0, float& c1, float& c2, float& c3,
                                         uint32_t a0, uint32_t a1, uint32_t a2, uint32_t a3,
                                         uint32_t b0, uint32_t b1) {
    asm volatile(
        "mma.sync.aligned.m16n8k8.row.col.f32.tf32.tf32.f32 "
        "{%0,%1,%2,%3},{%4,%5,%6,%7},{%8,%9},{%0,%1,%2,%3};"
        : "+f"(c0), "+f"(c1), "+f"(c2), "+f"(c3)
        : "r"(a0), "r"(a1), "r"(a2), "r"(a3), "r"(b0), "r"(b1));
}

__device__ __forceinline__ float sigm(float x) {
    return 1.0f / (1.0f + __expf(-x));
}

__device__ __forceinline__ unsigned ld_acq(const unsigned* p) {
    unsigned v;
    asm volatile("ld.acquire.gpu.global.u32 %0, [%1];" : "=r"(v) : "l"(p) : "memory");
    return v;
}

__device__ __forceinline__ void signal_release(unsigned* p) {
    unsigned old;
    asm volatile("atom.release.gpu.global.add.u32 %0, [%1], 1;"
                 : "=r"(old) : "l"(p) : "memory");
}

// ---------------- big GEMM: C[M,4096] = A[M,1024] * W[4096,1024]^T + bias ----------------
#define GA_STRIDE 20

__global__ __launch_bounds__(256, 2)
void gemm_xg_kernel(const float* __restrict__ A,
                    const float* __restrict__ W,
                    const float* __restrict__ b0,
                    const float* __restrict__ b1,
                    float* __restrict__ C)
{
    __shared__ float Ash[128 * GA_STRIDE];
    __shared__ float Bsh[128 * GA_STRIDE];

    const int tid  = threadIdx.x;
    const int wid  = tid >> 5, lane = tid & 31;
    const int g    = lane >> 2, t = lane & 3;
    const int wm   = wid & 1, wn = wid >> 1;
    const int cm   = blockIdx.y * 128;
    const int cn   = blockIdx.x * 128;

    float acc[4][4][4];
    #pragma unroll
    for (int i = 0; i < 4; i++)
        #pragma unroll
        for (int j = 0; j < 4; j++)
            #pragma unroll
            for (int q = 0; q < 4; q++) acc[i][j][q] = 0.0f;

    const int r0 = tid >> 2;
    const int q0 = tid & 3;

    const float* Ag = A + (size_t)cm * 1024;
    const float* Bg = W + (size_t)cn * 1024;

    for (int kk = 0; kk < 1024; kk += 16) {
        float4 av0 = *(const float4*)(Ag + (size_t)r0 * 1024 + kk + 4 * q0);
        float4 av1 = *(const float4*)(Ag + (size_t)(r0 + 64) * 1024 + kk + 4 * q0);
        float4 bv0 = *(const float4*)(Bg + (size_t)r0 * 1024 + kk + 4 * q0);
        float4 bv1 = *(const float4*)(Bg + (size_t)(r0 + 64) * 1024 + kk + 4 * q0);
        __syncthreads();
        {
            float4 w;
            w.x = f2tf32(av0.x); w.y = f2tf32(av0.y); w.z = f2tf32(av0.z); w.w = f2tf32(av0.w);
            *(float4*)(Ash + r0 * GA_STRIDE + 4 * q0) = w;
            w.x = f2tf32(av1.x); w.y = f2tf32(av1.y); w.z = f2tf32(av1.z); w.w = f2tf32(av1.w);
            *(float4*)(Ash + (r0 + 64) * GA_STRIDE + 4 * q0) = w;
            w.x = f2tf32(bv0.x); w.y = f2tf32(bv0.y); w.z = f2tf32(bv0.z); w.w = f2tf32(bv0.w);
            *(float4*)(Bsh + r0 * GA_STRIDE + 4 * q0) = w;
            w.x = f2tf32(bv1.x); w.y = f2tf32(bv1.y); w.z = f2tf32(bv1.z); w.w = f2tf32(bv1.w);
            *(float4*)(Bsh + (r0 + 64) * GA_STRIDE + 4 * q0) = w;
        }
        __syncthreads();

        #pragma unroll
        for (int kc = 0; kc < 16; kc += 8) {
            uint32_t af[4][4];
            uint32_t bf[4][2];
            #pragma unroll
            for (int mt = 0; mt < 4; mt++) {
                int rb = wm * 64 + mt * 16;
                af[mt][0] = __float_as_uint(Ash[(rb + g)     * GA_STRIDE + kc + t]);
                af[mt][1] = __float_as_uint(Ash[(rb + g + 8) * GA_STRIDE + kc + t]);
                af[mt][2] = __float_as_uint(Ash[(rb + g)     * GA_STRIDE + kc + t + 4]);
                af[mt][3] = __float_as_uint(Ash[(rb + g + 8) * GA_STRIDE + kc + t + 4]);
            }
            #pragma unroll
            for (int nt = 0; nt < 4; nt++) {
                int nb = wn * 32 + nt * 8 + g;
                bf[nt][0] = __float_as_uint(Bsh[nb * GA_STRIDE + kc + t]);
                bf[nt][1] = __float_as_uint(Bsh[nb * GA_STRIDE + kc + t + 4]);
            }
            #pragma unroll
            for (int mt = 0; mt < 4; mt++)
                #pragma unroll
                for (int nt = 0; nt < 4; nt++)
                    mma_tf32(acc[mt][nt][0], acc[mt][nt][1], acc[mt][nt][2], acc[mt][nt][3],
                             af[mt][0], af[mt][1], af[mt][2], af[mt][3],
                             bf[nt][0], bf[nt][1]);
        }
    }

    #pragma unroll
    for (int mt = 0; mt < 4; mt++) {
        #pragma unroll
        for (int nt = 0; nt < 4; nt++) {
            int m = cm + wm * 64 + mt * 16 + g;
            int n = cn + wn * 32 + nt * 8 + 2 * t;
            float bs0 = b0[n] + b1[n];
            float bs1 = b0[n + 1] + b1[n + 1];
            float2 v0 = make_float2(acc[mt][nt][0] + bs0, acc[mt][nt][1] + bs1);
            float2 v1 = make_float2(acc[mt][nt][2] + bs0, acc[mt][nt][3] + bs1);
            *(float2*)(C + (size_t)m * G4_ + n) = v0;
            *(float2*)(C + (size_t)(m + 8) * G4_ + n) = v1;
        }
    }
}

// ---------------- persistent LSTM scan (dataflow, no global barrier) ----------------
// 128 blocks x 512 threads. Block b owns gate-cols {gate*1024 + b*8 + j}, j in [0,8).
// Warp ks consumes K-slice 64 = h cols of producer blocks [8ks, 8ks+8).
// Producers publish per-block flags (monotonic, release); consumers acquire-poll
// only their 8 producers -> steps pipeline against each other chip-wide.
#define WS_  32768                 // W frag floats: 16ks*8s*4nt*32lane*2
#define RSTR 40
#define RS_  (16 * 32 * RSTR)      // reduction buffer floats
#define SCAN_SMEM ((WS_ + RS_) * 4)

__global__ __launch_bounds__(NTHR, 1)
void lstm_scan_kernel(const float* __restrict__ xg,     // [M, 4096]
                      const float* __restrict__ Whh,    // [4096, 1024]
                      const float* __restrict__ resid,  // [M, 1024] or nullptr
                      float* __restrict__ outseq)       // [M, 1024]
{
    extern __shared__ float sm[];
    float* Wsh = sm;            // WS_ floats
    float* Rsh = sm + WS_;      // RS_ floats

    const int tid  = threadIdx.x;
    const int bid  = blockIdx.x;
    const int wid  = tid >> 5, lane = tid & 31;
    const int g    = lane >> 2, t = lane & 3;
    const int ks   = wid;                 // 0..15, K-slice of 64

    // ---- fill W frags into shared (tf32-rounded), frag-permuted ----
    for (int e = tid; e < WS_; e += NTHR) {
        int rr = e & 1;
        int ln = (e >> 1) & 31;
        int nt = (e >> 6) & 3;
        int s  = (e >> 8) & 7;
        int kk = e >> 11;
        int n8 = ln >> 2, tt = ln & 3;
        int j32  = nt * 8 + n8;
        int wrow = (j32 >> 3) * 1024 + bid * 8 + (j32 & 7);
        int k    = kk * 64 + s * 8 + tt + rr * 4;
        Wsh[e] = f2tf32(Whh[(size_t)wrow * 1024 + k]);
    }

    // elementwise ownership (tid < 256): (batch eb, local col ej)
    const int eb   = tid >> 3;
    const int ej   = tid & 7;
    const int hcol = bid * 8 + ej;
    const int fmt  = eb >> 4;
    const int foff = (((bid * 2 + fmt) * 32 + (eb & 7) * 4 + (ej & 3)) << 2)
                     + ((eb >> 3) & 1) + ((ej >> 2) << 1);

    // init h(0) = 0 in buf0 and publish (flag[0][bid]: 0 -> 1)
    if (tid < 256) g_hA[0][foff] = 0.0f;
    float c_state = 0.0f;
    __threadfence();
    __syncthreads();
    if (tid == 0) signal_release(&g_flag[0][bid * 8]);

    int p = 0;
    for (int ts = 0; ts < T_; ts++) {
        // prefetch xg + residual (independent of h)
        float xv0 = 0.f, xv1 = 0.f, xv2 = 0.f, xv3 = 0.f, rv = 0.f;
        size_t mrow = 0;
        if (tid < 256) {
            mrow = (size_t)eb * T_ + ts;
            const float* xp = xg + mrow * G4_ + hcol;
            xv0 = __ldcs(xp);
            xv1 = __ldcs(xp + 1024);
            xv2 = __ldcs(xp + 2048);
            xv3 = __ldcs(xp + 3072);
            if (resid) rv = __ldcs(resid + mrow * H_ + hcol);
        }

        // ---- wait for this warp's 8 producers (buf p written (ts/2)+1 times) ----
        const unsigned target = (unsigned)(ts >> 1) + 1u;
        if (lane == 0) {
            #pragma unroll
            for (int j = 0; j < 8; j++) {
                const unsigned* fp = &g_flag[p][(ks * 8 + j) * 8];
                while (ld_acq(fp) < target) { }
            }
        }
        __syncwarp();

        float acc[2][4][4];
        #pragma unroll
        for (int mt = 0; mt < 2; mt++)
            #pragma unroll
            for (int nt = 0; nt < 4; nt++)
                #pragma unroll
                for (int q = 0; q < 4; q++) acc[mt][nt][q] = 0.0f;

        const float4* hA = (const float4*)g_hA[p];
        #pragma unroll
        for (int si = 0; si < 8; si++) {
            int s = ks * 8 + si;
            float4 a0 = __ldcg(hA + (s * 2 + 0) * 32 + lane);
            float4 a1 = __ldcg(hA + (s * 2 + 1) * 32 + lane);
            #pragma unroll
            for (int nt = 0; nt < 4; nt++) {
                float2 w = *(const float2*)(Wsh + (((((ks * 8 + si) * 4) + nt) * 32 + lane) << 1));
                mma_tf32(acc[0][nt][0], acc[0][nt][1], acc[0][nt][2], acc[0][nt][3],
                         __float_as_uint(a0.x), __float_as_uint(a0.y),
                         __float_as_uint(a0.z), __float_as_uint(a0.w),
                         __float_as_uint(w.x), __float_as_uint(w.y));
                mma_tf32(acc[1][nt][0], acc[1][nt][1], acc[1][nt][2], acc[1][nt][3],
                         __float_as_uint(a1.x), __float_as_uint(a1.y),
                         __float_as_uint(a1.z), __float_as_uint(a1.w),
                         __float_as_uint(w.x), __float_as_uint(w.y));
            }
        }

        // store K-partials to Rsh
        #pragma unroll
        for (int mt = 0; mt < 2; mt++) {
            #pragma unroll
            for (int nt = 0; nt < 4; nt++) {
                int row = mt * 16 + g;
                int col = nt * 8 + 2 * t;
                *(float2*)(Rsh + (ks * 32 + row) * RSTR + col) =
                    make_float2(acc[mt][nt][0], acc[mt][nt][1]);
                *(float2*)(Rsh + (ks * 32 + row + 8) * RSTR + col) =
                    make_float2(acc[mt][nt][2], acc[mt][nt][3]);
            }
        }
        __syncthreads();

        // 16-way reduce + LSTM cell (256 active threads)
        if (tid < 256) {
            float s0 = xv0, s1 = xv1, s2 = xv2, s3 = xv3;
            #pragma unroll
            for (int kk = 0; kk < 16; kk++) {
                const float* rp = Rsh + (kk * 32 + eb) * RSTR + ej;
                s0 += rp[0];
                s1 += rp[8];
                s2 += rp[16];
                s3 += rp[24];
            }
            float iv = sigm(s0);
            float fv = sigm(s1);
            float gv = tanhf(s2);
            float ov = sigm(s3);
            c_state = fv * c_state + iv * gv;
            float hval = ov * tanhf(c_state);

            g_hA[1 - p][foff] = f2tf32(hval);          // frag-permuted recurrent copy
            outseq[mrow * H_ + hcol] = hval + rv;      // normal-layout output (+residual)
        }

        // publish: writes to buf (1-p) visible before flag bump
        __threadfence();
        __syncthreads();
        if (tid == 0) signal_release(&g_flag[1 - p][bid * 8]);

        p ^= 1;
    }
}

// ---------------- launch ----------------
extern "C" void kernel_launch(void* const* d_in, const int* in_sizes, int n_in,
                              void* d_out, int out_size) {
    const float* x    = (const float*)d_in[0];
    const float* Wih0 = (const float*)d_in[1];
    const float* Whh0 = (const float*)d_in[2];
    const float* bih0 = (const float*)d_in[3];
    const float* bhh0 = (const float*)d_in[4];
    const float* Wih1 = (const float*)d_in[5];
    const float* Whh1 = (const float*)d_in[6];
    const float* bih1 = (const float*)d_in[7];
    const float* bhh1 = (const float*)d_in[8];
    float* out = (float*)d_out;

    cudaFuncSetAttribute(lstm_scan_kernel,
                         cudaFuncAttributeMaxDynamicSharedMemorySize, SCAN_SMEM);

    void* p;
    cudaGetSymbolAddress(&p, g_xg);    float* xg = (float*)p;
    cudaGetSymbolAddress(&p, g_h0seq); float* h0 = (float*)p;
    cudaGetSymbolAddress(&p, g_flag);  unsigned* flg = (unsigned*)p;

    dim3 gg(32, 128);  // (N tiles, M tiles)

    // layer 0
    cudaMemsetAsync(flg, 0, sizeof(unsigned) * 2 * NBLK * 8);
    gemm_xg_kernel<<<gg, 256>>>(x, Wih0, bih0, bhh0, xg);
    lstm_scan_kernel<<<NBLK, NTHR, SCAN_SMEM>>>(xg, Whh0, nullptr, h0);
    // layer 1 (+ residual into final out)
    cudaMemsetAsync(flg, 0, sizeof(unsigned) * 2 * NBLK * 8);
    gemm_xg_kernel<<<gg, 256>>>(h0, Wih1, bih1, bhh1, xg);
    lstm_scan_kernel<<<NBLK, NTHR, SCAN_SMEM>>>(xg, Whh1, h0, out);
}

// round 5
// speedup vs baseline: 1.3613x; 1.3613x over previous
#include <cuda_runtime.h>
#include <cuda_fp16.h>
#include <cstdint>

#define B_  32
#define T_  512
#define H_  1024
#define G4_ 4096
#define M_  (B_ * T_)   // 16384
#define NBLK 128
#define NTHR 512

// ---------------- static device scratch (no allocations allowed) ----------------
__device__ float g_xg[(size_t)M_ * G4_];     // gate preactivations for current layer
__device__ float g_h0seq[(size_t)M_ * H_];   // layer-0 output sequence (normal layout)
// frag-permuted recurrent h (fp16, packed half2), double buffered:
// u32 index = ((c*2 + mt)*32 + lane)*4 + ridx,  c = k-chunk(16) 0..63
__device__ unsigned g_hH[2][16384];          // 64 KB per buffer
__device__ unsigned g_arrive;

// ---------------- helpers ----------------
__device__ __forceinline__ float f2tf32(float x) {
    uint32_t r;
    asm("cvt.rna.tf32.f32 %0, %1;" : "=r"(r) : "f"(x));
    return __uint_as_float(r);
}

__device__ __forceinline__ void mma_tf32(float& c0, float& c1, float& c2, float& c3,
                                         uint32_t a0, uint32_t a1, uint32_t a2, uint32_t a3,
                                         uint32_t b0, uint32_t b1) {
    asm volatile(
        "mma.sync.aligned.m16n8k8.row.col.f32.tf32.tf32.f32 "
        "{%0,%1,%2,%3},{%4,%5,%6,%7},{%8,%9},{%0,%1,%2,%3};"
        : "+f"(c0), "+f"(c1), "+f"(c2), "+f"(c3)
        : "r"(a0), "r"(a1), "r"(a2), "r"(a3), "r"(b0), "r"(b1));
}

__device__ __forceinline__ void mma_f16(float& c0, float& c1, float& c2, float& c3,
                                        uint32_t a0, uint32_t a1, uint32_t a2, uint32_t a3,
                                        uint32_t b0, uint32_t b1) {
    asm volatile(
        "mma.sync.aligned.m16n8k16.row.col.f32.f16.f16.f32 "
        "{%0,%1,%2,%3},{%4,%5,%6,%7},{%8,%9},{%0,%1,%2,%3};"
        : "+f"(c0), "+f"(c1), "+f"(c2), "+f"(c3)
        : "r"(a0), "r"(a1), "r"(a2), "r"(a3), "r"(b0), "r"(b1));
}

__device__ __forceinline__ float sigm(float x) {
    return 1.0f / (1.0f + __expf(-x));
}

// release/acquire grid barrier on a monotonic counter (reset between launches)
__device__ __forceinline__ void grid_barrier(unsigned target) {
    __syncthreads();
    if (threadIdx.x == 0) {
        unsigned old;
        asm volatile("atom.release.gpu.global.add.u32 %0, [%1], 1;"
                     : "=r"(old) : "l"(&g_arrive) : "memory");
        unsigned v;
        do {
            asm volatile("ld.acquire.gpu.global.u32 %0, [%1];"
                         : "=r"(v) : "l"(&g_arrive) : "memory");
        } while (v < target);
    }
    __syncthreads();
}

// ---------------- big GEMM: C[M,4096] = A[M,1024] * W[4096,1024]^T + bias ----------------
#define GA_STRIDE 20

__global__ __launch_bounds__(256, 2)
void gemm_xg_kernel(const float* __restrict__ A,
                    const float* __restrict__ W,
                    const float* __restrict__ b0,
                    const float* __restrict__ b1,
                    float* __restrict__ C)
{
    __shared__ float Ash[128 * GA_STRIDE];
    __shared__ float Bsh[128 * GA_STRIDE];

    const int tid  = threadIdx.x;
    const int wid  = tid >> 5, lane = tid & 31;
    const int g    = lane >> 2, t = lane & 3;
    const int wm   = wid & 1, wn = wid >> 1;
    const int cm   = blockIdx.y * 128;
    const int cn   = blockIdx.x * 128;

    float acc[4][4][4];
    #pragma unroll
    for (int i = 0; i < 4; i++)
        #pragma unroll
        for (int j = 0; j < 4; j++)
            #pragma unroll
            for (int q = 0; q < 4; q++) acc[i][j][q] = 0.0f;

    const int r0 = tid >> 2;
    const int q0 = tid & 3;

    const float* Ag = A + (size_t)cm * 1024;
    const float* Bg = W + (size_t)cn * 1024;

    for (int kk = 0; kk < 1024; kk += 16) {
        float4 av0 = *(const float4*)(Ag + (size_t)r0 * 1024 + kk + 4 * q0);
        float4 av1 = *(const float4*)(Ag + (size_t)(r0 + 64) * 1024 + kk + 4 * q0);
        float4 bv0 = *(const float4*)(Bg + (size_t)r0 * 1024 + kk + 4 * q0);
        float4 bv1 = *(const float4*)(Bg + (size_t)(r0 + 64) * 1024 + kk + 4 * q0);
        __syncthreads();
        {
            float4 w;
            w.x = f2tf32(av0.x); w.y = f2tf32(av0.y); w.z = f2tf32(av0.z); w.w = f2tf32(av0.w);
            *(float4*)(Ash + r0 * GA_STRIDE + 4 * q0) = w;
            w.x = f2tf32(av1.x); w.y = f2tf32(av1.y); w.z = f2tf32(av1.z); w.w = f2tf32(av1.w);
            *(float4*)(Ash + (r0 + 64) * GA_STRIDE + 4 * q0) = w;
            w.x = f2tf32(bv0.x); w.y = f2tf32(bv0.y); w.z = f2tf32(bv0.z); w.w = f2tf32(bv0.w);
            *(float4*)(Bsh + r0 * GA_STRIDE + 4 * q0) = w;
            w.x = f2tf32(bv1.x); w.y = f2tf32(bv1.y); w.z = f2tf32(bv1.z); w.w = f2tf32(bv1.w);
            *(float4*)(Bsh + (r0 + 64) * GA_STRIDE + 4 * q0) = w;
        }
        __syncthreads();

        #pragma unroll
        for (int kc = 0; kc < 16; kc += 8) {
            uint32_t af[4][4];
            uint32_t bf[4][2];
            #pragma unroll
            for (int mt = 0; mt < 4; mt++) {
                int rb = wm * 64 + mt * 16;
                af[mt][0] = __float_as_uint(Ash[(rb + g)     * GA_STRIDE + kc + t]);
                af[mt][1] = __float_as_uint(Ash[(rb + g + 8) * GA_STRIDE + kc + t]);
                af[mt][2] = __float_as_uint(Ash[(rb + g)     * GA_STRIDE + kc + t + 4]);
                af[mt][3] = __float_as_uint(Ash[(rb + g + 8) * GA_STRIDE + kc + t + 4]);
            }
            #pragma unroll
            for (int nt = 0; nt < 4; nt++) {
                int nb = wn * 32 + nt * 8 + g;
                bf[nt][0] = __float_as_uint(Bsh[nb * GA_STRIDE + kc + t]);
                bf[nt][1] = __float_as_uint(Bsh[nb * GA_STRIDE + kc + t + 4]);
            }
            #pragma unroll
            for (int mt = 0; mt < 4; mt++)
                #pragma unroll
                for (int nt = 0; nt < 4; nt++)
                    mma_tf32(acc[mt][nt][0], acc[mt][nt][1], acc[mt][nt][2], acc[mt][nt][3],
                             af[mt][0], af[mt][1], af[mt][2], af[mt][3],
                             bf[nt][0], bf[nt][1]);
        }
    }

    #pragma unroll
    for (int mt = 0; mt < 4; mt++) {
        #pragma unroll
        for (int nt = 0; nt < 4; nt++) {
            int m = cm + wm * 64 + mt * 16 + g;
            int n = cn + wn * 32 + nt * 8 + 2 * t;
            float bs0 = b0[n] + b1[n];
            float bs1 = b0[n + 1] + b1[n + 1];
            float2 v0 = make_float2(acc[mt][nt][0] + bs0, acc[mt][nt][1] + bs1);
            float2 v1 = make_float2(acc[mt][nt][2] + bs0, acc[mt][nt][3] + bs1);
            *(float2*)(C + (size_t)m * G4_ + n) = v0;
            *(float2*)(C + (size_t)(m + 8) * G4_ + n) = v1;
        }
    }
}

// ---------------- persistent LSTM scan (fp16 recurrent mma, grid barrier) ----------------
// 128 blocks x 512 threads. Block b owns gate-cols {gate*1024 + b*8 + j}, j in [0,8).
// 16 warps; warp ks consumes K-slice [64ks, 64ks+64) = 4 chunks of 16.
// A (=h, fp16 packed) loaded as 8x LDG.128 from frag-permuted gmem; W (B frags,
// fp16 packed) from smem LDS.64 conflict-free; 16-way K reduce via padded smem.
#define WS_  16384                 // W frag u32s: 16ks*4si*4nt*32lane*2
#define RSTR 40
#define RS_  (16 * 32 * RSTR)      // reduction buffer floats
#define SCAN_SMEM (WS_ * 4 + RS_ * 4)   // 65536 + 81920 = 147456 B

__global__ __launch_bounds__(NTHR, 1)
void lstm_scan_kernel(const float* __restrict__ xg,     // [M, 4096]
                      const float* __restrict__ Whh,    // [4096, 1024]
                      const float* __restrict__ resid,  // [M, 1024] or nullptr
                      float* __restrict__ outseq)       // [M, 1024]
{
    extern __shared__ float sm[];
    unsigned* Wsh = (unsigned*)sm;        // WS_ u32
    float*    Rsh = sm + WS_;             // RS_ floats

    const int tid  = threadIdx.x;
    const int bid  = blockIdx.x;
    const int wid  = tid >> 5, lane = tid & 31;
    const int g    = lane >> 2, t = lane & 3;
    const int ks   = wid;                 // 0..15, K-slice of 64

    // ---- fill W frags (fp16 packed half2), frag-permuted for m16n8k16 ----
    // e = ((((ks*4+si)*4+nt)*32)+lane)*2 + rr
    for (int e = tid; e < WS_; e += NTHR) {
        int rr = e & 1;
        int ln = (e >> 1) & 31;
        int nt = (e >> 6) & 3;
        int si = (e >> 8) & 3;
        int kk = e >> 10;
        int gg = ln >> 2, tt = ln & 3;
        int n32  = nt * 8 + gg;                              // 0..31 local gate-col
        int wrow = (n32 >> 3) * 1024 + bid * 8 + (n32 & 7);  // Whh row (gate-major)
        int k0   = kk * 64 + si * 16 + 2 * tt + rr * 8;
        __half h0 = __float2half_rn(Whh[(size_t)wrow * 1024 + k0]);
        __half h1 = __float2half_rn(Whh[(size_t)wrow * 1024 + k0 + 1]);
        __half2 hv = __halves2half2(h0, h1);
        Wsh[e] = *(unsigned*)&hv;
    }

    // elementwise ownership (tid < 256): (batch eb, local col ej)
    const int eb   = tid >> 3;
    const int ej   = tid & 7;
    const int hcol = bid * 8 + ej;
    // frag-permuted u32 slot for the half2 pair (ej even thread writes)
    const int c_   = bid >> 1;
    const int fmt  = eb >> 4;
    const int ridx = (bid & 1) * 2 + ((eb >> 3) & 1);
    const int foff = (((c_ * 2 + fmt) * 32) + (eb & 7) * 4 + (ej >> 1)) * 4 + ridx;

    // init h(0) = 0 in buf0
    if (tid < 256 && (ej & 1) == 0) g_hH[0][foff] = 0u;
    float c_state = 0.0f;

    unsigned phase = 1;
    grid_barrier(phase * NBLK);

    int p = 0;
    for (int ts = 0; ts < T_; ts++) {
        // prefetch xg + residual (independent of h; overlaps barrier/loads)
        float xv0 = 0.f, xv1 = 0.f, xv2 = 0.f, xv3 = 0.f, rv = 0.f;
        size_t mrow = 0;
        if (tid < 256) {
            mrow = (size_t)eb * T_ + ts;
            const float* xp = xg + mrow * G4_ + hcol;
            xv0 = __ldcs(xp);
            xv1 = __ldcs(xp + 1024);
            xv2 = __ldcs(xp + 2048);
            xv3 = __ldcs(xp + 3072);
            if (resid) rv = __ldcs(resid + mrow * H_ + hcol);
        }

        // ---- batched A loads (8x LDG.128) for maximum MLP ----
        const uint4* hA = (const uint4*)g_hH[p];
        uint4 a[4][2];
        #pragma unroll
        for (int si = 0; si < 4; si++) {
            int c = ks * 4 + si;
            a[si][0] = __ldcg(hA + (c * 2 + 0) * 32 + lane);
            a[si][1] = __ldcg(hA + (c * 2 + 1) * 32 + lane);
        }

        float acc[2][4][4];
        #pragma unroll
        for (int mt = 0; mt < 2; mt++)
            #pragma unroll
            for (int nt = 0; nt < 4; nt++)
                #pragma unroll
                for (int q = 0; q < 4; q++) acc[mt][nt][q] = 0.0f;

        #pragma unroll
        for (int si = 0; si < 4; si++) {
            #pragma unroll
            for (int nt = 0; nt < 4; nt++) {
                uint2 w = *(const uint2*)(Wsh + ((((ks * 4 + si) * 4 + nt) * 32 + lane) << 1));
                mma_f16(acc[0][nt][0], acc[0][nt][1], acc[0][nt][2], acc[0][nt][3],
                        a[si][0].x, a[si][0].y, a[si][0].z, a[si][0].w, w.x, w.y);
                mma_f16(acc[1][nt][0], acc[1][nt][1], acc[1][nt][2], acc[1][nt][3],
                        a[si][1].x, a[si][1].y, a[si][1].z, a[si][1].w, w.x, w.y);
            }
        }

        // store K-partials to Rsh
        #pragma unroll
        for (int mt = 0; mt < 2; mt++) {
            #pragma unroll
            for (int nt = 0; nt < 4; nt++) {
                int row = mt * 16 + g;
                int col = nt * 8 + 2 * t;
                *(float2*)(Rsh + (ks * 32 + row) * RSTR + col) =
                    make_float2(acc[mt][nt][0], acc[mt][nt][1]);
                *(float2*)(Rsh + (ks * 32 + row + 8) * RSTR + col) =
                    make_float2(acc[mt][nt][2], acc[mt][nt][3]);
            }
        }
        __syncthreads();

        // 16-way reduce + LSTM cell (256 active threads)
        if (tid < 256) {
            float s0 = xv0, s1 = xv1, s2 = xv2, s3 = xv3;
            #pragma unroll
            for (int kk = 0; kk < 16; kk++) {
                const float* rp = Rsh + (kk * 32 + eb) * RSTR + ej;
                s0 += rp[0];
                s1 += rp[8];
                s2 += rp[16];
                s3 += rp[24];
            }
            float iv = sigm(s0);
            float fv = sigm(s1);
            float gv = tanhf(s2);
            float ov = sigm(s3);
            c_state = fv * c_state + iv * gv;
            float hval = ov * tanhf(c_state);

            // publish h (fp16, frag-permuted): pair adjacent cols into one u32
            unsigned hbits = (unsigned)__half_as_ushort(__float2half_rn(hval));
            unsigned obits = __shfl_xor_sync(0xffffffffu, hbits, 1);
            if ((ej & 1) == 0) {
                unsigned packed = (hbits & 0xffffu) | (obits << 16);
                g_hH[1 - p][foff] = packed;
            }
            outseq[mrow * H_ + hcol] = hval + rv;   // fp32 output (+residual)
        }

        phase++;
        grid_barrier(phase * NBLK);
        p ^= 1;
    }
}

// ---------------- launch ----------------
extern "C" void kernel_launch(void* const* d_in, const int* in_sizes, int n_in,
                              void* d_out, int out_size) {
    const float* x    = (const float*)d_in[0];
    const float* Wih0 = (const float*)d_in[1];
    const float* Whh0 = (const float*)d_in[2];
    const float* bih0 = (const float*)d_in[3];
    const float* bhh0 = (const float*)d_in[4];
    const float* Wih1 = (const float*)d_in[5];
    const float* Whh1 = (const float*)d_in[6];
    const float* bih1 = (const float*)d_in[7];
    const float* bhh1 = (const float*)d_in[8];
    float* out = (float*)d_out;

    cudaFuncSetAttribute(lstm_scan_kernel,
                         cudaFuncAttributeMaxDynamicSharedMemorySize, SCAN_SMEM);

    void* p;
    cudaGetSymbolAddress(&p, g_xg);     float* xg = (float*)p;
    cudaGetSymbolAddress(&p, g_h0seq);  float* h0 = (float*)p;
    cudaGetSymbolAddress(&p, g_arrive); unsigned* arr = (unsigned*)p;

    dim3 gg(32, 128);  // (N tiles, M tiles)

    // layer 0
    cudaMemsetAsync(arr, 0, sizeof(unsigned));
    gemm_xg_kernel<<<gg, 256>>>(x, Wih0, bih0, bhh0, xg);
    lstm_scan_kernel<<<NBLK, NTHR, SCAN_SMEM>>>(xg, Whh0, nullptr, h0);
    // layer 1 (+ residual into final out)
    cudaMemsetAsync(arr, 0, sizeof(unsigned));
    gemm_xg_kernel<<<gg, 256>>>(h0, Wih1, bih1, bhh1, xg);
    lstm_scan_kernel<<<NBLK, NTHR, SCAN_SMEM>>>(xg, Whh1, h0, out);
}

// round 6
// speedup vs baseline: 1.3662x; 1.0036x over previous
#include <cuda_runtime.h>
#include <cuda_fp16.h>
#include <cstdint>

#define B_  32
#define T_  512
#define H_  1024
#define G4_ 4096
#define M_  (B_ * T_)   // 16384
#define NBLK 128
#define NTHR 512
#define NCNT 16          // striped barrier counters
#define CSTR 64          // counter stride in u32 (256 B -> distinct LTS slices)
#define BLKS_PER_CNT (NBLK / NCNT)

// ---------------- static device scratch (no allocations allowed) ----------------
__device__ float g_xg[(size_t)M_ * G4_];     // gate preactivations for current layer
__device__ float g_h0seq[(size_t)M_ * H_];   // layer-0 output sequence (normal layout)
// frag-permuted recurrent h (fp16, packed half2), double buffered:
// u32 index = ((c*2 + mt)*32 + lane)*4 + ridx,  c = k-chunk(16) 0..63
__device__ unsigned g_hH[2][16384];          // 64 KB per buffer
__device__ unsigned g_arrive[NCNT * CSTR];   // striped monotonic counters

// ---------------- helpers ----------------
__device__ __forceinline__ float f2tf32(float x) {
    uint32_t r;
    asm("cvt.rna.tf32.f32 %0, %1;" : "=r"(r) : "f"(x));
    return __uint_as_float(r);
}

__device__ __forceinline__ void mma_tf32(float& c0, float& c1, float& c2, float& c3,
                                         uint32_t a0, uint32_t a1, uint32_t a2, uint32_t a3,
                                         uint32_t b0, uint32_t b1) {
    asm volatile(
        "mma.sync.aligned.m16n8k8.row.col.f32.tf32.tf32.f32 "
        "{%0,%1,%2,%3},{%4,%5,%6,%7},{%8,%9},{%0,%1,%2,%3};"
        : "+f"(c0), "+f"(c1), "+f"(c2), "+f"(c3)
        : "r"(a0), "r"(a1), "r"(a2), "r"(a3), "r"(b0), "r"(b1));
}

__device__ __forceinline__ void mma_f16(float& c0, float& c1, float& c2, float& c3,
                                        uint32_t a0, uint32_t a1, uint32_t a2, uint32_t a3,
                                        uint32_t b0, uint32_t b1) {
    asm volatile(
        "mma.sync.aligned.m16n8k16.row.col.f32.f16.f16.f32 "
        "{%0,%1,%2,%3},{%4,%5,%6,%7},{%8,%9},{%0,%1,%2,%3};"
        : "+f"(c0), "+f"(c1), "+f"(c2), "+f"(c3)
        : "r"(a0), "r"(a1), "r"(a2), "r"(a3), "r"(b0), "r"(b1));
}

__device__ __forceinline__ float sigm(float x) {
    return 1.0f / (1.0f + __expf(-x));
}

// striped release/acquire grid barrier: 16 counters, 8 blocks each (monotonic)
__device__ __forceinline__ void grid_barrier(unsigned phase) {
    __syncthreads();
    if (threadIdx.x == 0) {
        asm volatile("red.release.gpu.global.add.u32 [%0], 1;"
                     :: "l"(&g_arrive[(blockIdx.x & (NCNT - 1)) * CSTR]) : "memory");
    }
    if (threadIdx.x < NCNT) {
        const unsigned target = phase * BLKS_PER_CNT;
        const unsigned* cp = &g_arrive[threadIdx.x * CSTR];
        unsigned v;
        do {
            asm volatile("ld.acquire.gpu.global.u32 %0, [%1];"
                         : "=r"(v) : "l"(cp) : "memory");
        } while (v < target);
    }
    __syncthreads();
}

// ---------------- big GEMM: C[M,4096] = A[M,1024] * W[4096,1024]^T + bias ----------------
#define GA_STRIDE 20

__global__ __launch_bounds__(256, 2)
void gemm_xg_kernel(const float* __restrict__ A,
                    const float* __restrict__ W,
                    const float* __restrict__ b0,
                    const float* __restrict__ b1,
                    float* __restrict__ C)
{
    __shared__ float Ash[128 * GA_STRIDE];
    __shared__ float Bsh[128 * GA_STRIDE];

    const int tid  = threadIdx.x;
    const int wid  = tid >> 5, lane = tid & 31;
    const int g    = lane >> 2, t = lane & 3;
    const int wm   = wid & 1, wn = wid >> 1;
    const int cm   = blockIdx.y * 128;
    const int cn   = blockIdx.x * 128;

    float acc[4][4][4];
    #pragma unroll
    for (int i = 0; i < 4; i++)
        #pragma unroll
        for (int j = 0; j < 4; j++)
            #pragma unroll
            for (int q = 0; q < 4; q++) acc[i][j][q] = 0.0f;

    const int r0 = tid >> 2;
    const int q0 = tid & 3;

    const float* Ag = A + (size_t)cm * 1024;
    const float* Bg = W + (size_t)cn * 1024;

    for (int kk = 0; kk < 1024; kk += 16) {
        float4 av0 = *(const float4*)(Ag + (size_t)r0 * 1024 + kk + 4 * q0);
        float4 av1 = *(const float4*)(Ag + (size_t)(r0 + 64) * 1024 + kk + 4 * q0);
        float4 bv0 = *(const float4*)(Bg + (size_t)r0 * 1024 + kk + 4 * q0);
        float4 bv1 = *(const float4*)(Bg + (size_t)(r0 + 64) * 1024 + kk + 4 * q0);
        __syncthreads();
        {
            float4 w;
            w.x = f2tf32(av0.x); w.y = f2tf32(av0.y); w.z = f2tf32(av0.z); w.w = f2tf32(av0.w);
            *(float4*)(Ash + r0 * GA_STRIDE + 4 * q0) = w;
            w.x = f2tf32(av1.x); w.y = f2tf32(av1.y); w.z = f2tf32(av1.z); w.w = f2tf32(av1.w);
            *(float4*)(Ash + (r0 + 64) * GA_STRIDE + 4 * q0) = w;
            w.x = f2tf32(bv0.x); w.y = f2tf32(bv0.y); w.z = f2tf32(bv0.z); w.w = f2tf32(bv0.w);
            *(float4*)(Bsh + r0 * GA_STRIDE + 4 * q0) = w;
            w.x = f2tf32(bv1.x); w.y = f2tf32(bv1.y); w.z = f2tf32(bv1.z); w.w = f2tf32(bv1.w);
            *(float4*)(Bsh + (r0 + 64) * GA_STRIDE + 4 * q0) = w;
        }
        __syncthreads();

        #pragma unroll
        for (int kc = 0; kc < 16; kc += 8) {
            uint32_t af[4][4];
            uint32_t bf[4][2];
            #pragma unroll
            for (int mt = 0; mt < 4; mt++) {
                int rb = wm * 64 + mt * 16;
                af[mt][0] = __float_as_uint(Ash[(rb + g)     * GA_STRIDE + kc + t]);
                af[mt][1] = __float_as_uint(Ash[(rb + g + 8) * GA_STRIDE + kc + t]);
                af[mt][2] = __float_as_uint(Ash[(rb + g)     * GA_STRIDE + kc + t + 4]);
                af[mt][3] = __float_as_uint(Ash[(rb + g + 8) * GA_STRIDE + kc + t + 4]);
            }
            #pragma unroll
            for (int nt = 0; nt < 4; nt++) {
                int nb = wn * 32 + nt * 8 + g;
                bf[nt][0] = __float_as_uint(Bsh[nb * GA_STRIDE + kc + t]);
                bf[nt][1] = __float_as_uint(Bsh[nb * GA_STRIDE + kc + t + 4]);
            }
            #pragma unroll
            for (int mt = 0; mt < 4; mt++)
                #pragma unroll
                for (int nt = 0; nt < 4; nt++)
                    mma_tf32(acc[mt][nt][0], acc[mt][nt][1], acc[mt][nt][2], acc[mt][nt][3],
                             af[mt][0], af[mt][1], af[mt][2], af[mt][3],
                             bf[nt][0], bf[nt][1]);
        }
    }

    #pragma unroll
    for (int mt = 0; mt < 4; mt++) {
        #pragma unroll
        for (int nt = 0; nt < 4; nt++) {
            int m = cm + wm * 64 + mt * 16 + g;
            int n = cn + wn * 32 + nt * 8 + 2 * t;
            float bs0 = b0[n] + b1[n];
            float bs1 = b0[n + 1] + b1[n + 1];
            float2 v0 = make_float2(acc[mt][nt][0] + bs0, acc[mt][nt][1] + bs1);
            float2 v1 = make_float2(acc[mt][nt][2] + bs0, acc[mt][nt][3] + bs1);
            *(float2*)(C + (size_t)m * G4_ + n) = v0;
            *(float2*)(C + (size_t)(m + 8) * G4_ + n) = v1;
        }
    }
}

// ---------------- persistent LSTM scan (fp16 recurrent mma, striped barrier) ----------------
#define WS_  16384                 // W frag u32s: 16ks*4si*4nt*32lane*2
#define RSTR 40
#define RS_  (16 * 32 * RSTR)      // reduction buffer floats
#define SCAN_SMEM (WS_ * 4 + RS_ * 4)   // 147456 B

__global__ __launch_bounds__(NTHR, 1)
void lstm_scan_kernel(const float* __restrict__ xg,     // [M, 4096]
                      const float* __restrict__ Whh,    // [4096, 1024]
                      const float* __restrict__ resid,  // [M, 1024] or nullptr
                      float* __restrict__ outseq)       // [M, 1024]
{
    extern __shared__ float sm[];
    unsigned* Wsh = (unsigned*)sm;        // WS_ u32
    float*    Rsh = sm + WS_;             // RS_ floats

    const int tid  = threadIdx.x;
    const int bid  = blockIdx.x;
    const int wid  = tid >> 5, lane = tid & 31;
    const int g    = lane >> 2, t = lane & 3;
    const int ks   = wid;                 // 0..15, K-slice of 64

    // ---- fill W frags (fp16 packed half2), frag-permuted for m16n8k16 ----
    for (int e = tid; e < WS_; e += NTHR) {
        int rr = e & 1;
        int ln = (e >> 1) & 31;
        int nt = (e >> 6) & 3;
        int si = (e >> 8) & 3;
        int kk = e >> 10;
        int gg = ln >> 2, tt = ln & 3;
        int n32  = nt * 8 + gg;                              // 0..31 local gate-col
        int wrow = (n32 >> 3) * 1024 + bid * 8 + (n32 & 7);  // Whh row (gate-major)
        int k0   = kk * 64 + si * 16 + 2 * tt + rr * 8;
        __half h0 = __float2half_rn(Whh[(size_t)wrow * 1024 + k0]);
        __half h1 = __float2half_rn(Whh[(size_t)wrow * 1024 + k0 + 1]);
        __half2 hv = __halves2half2(h0, h1);
        Wsh[e] = *(unsigned*)&hv;
    }

    // elementwise ownership (tid < 256): (batch eb, local col ej)
    const int eb   = tid >> 3;
    const int ej   = tid & 7;
    const int hcol = bid * 8 + ej;
    const int c_   = bid >> 1;
    const int fmt  = eb >> 4;
    const int ridx = (bid & 1) * 2 + ((eb >> 3) & 1);
    const int foff = (((c_ * 2 + fmt) * 32) + (eb & 7) * 4 + (ej >> 1)) * 4 + ridx;

    // init h(0) = 0 in buf0
    if (tid < 256 && (ej & 1) == 0) g_hH[0][foff] = 0u;
    float c_state = 0.0f;

    unsigned phase = 1;
    grid_barrier(phase);

    int p = 0;
    for (int ts = 0; ts < T_; ts++) {
        // prefetch xg + residual (independent of h; overlaps barrier/loads)
        float xv0 = 0.f, xv1 = 0.f, xv2 = 0.f, xv3 = 0.f, rv = 0.f;
        size_t mrow = 0;
        if (tid < 256) {
            mrow = (size_t)eb * T_ + ts;
            const float* xp = xg + mrow * G4_ + hcol;
            xv0 = __ldcs(xp);
            xv1 = __ldcs(xp + 1024);
            xv2 = __ldcs(xp + 2048);
            xv3 = __ldcs(xp + 3072);
            if (resid) rv = __ldcs(resid + mrow * H_ + hcol);
        }

        // ---- batched A loads (8x LDG.128) for maximum MLP ----
        const uint4* hA = (const uint4*)g_hH[p];
        uint4 a[4][2];
        #pragma unroll
        for (int si = 0; si < 4; si++) {
            int c = ks * 4 + si;
            a[si][0] = __ldcg(hA + (c * 2 + 0) * 32 + lane);
            a[si][1] = __ldcg(hA + (c * 2 + 1) * 32 + lane);
        }

        float acc[2][4][4];
        #pragma unroll
        for (int mt = 0; mt < 2; mt++)
            #pragma unroll
            for (int nt = 0; nt < 4; nt++)
                #pragma unroll
                for (int q = 0; q < 4; q++) acc[mt][nt][q] = 0.0f;

        #pragma unroll
        for (int si = 0; si < 4; si++) {
            #pragma unroll
            for (int nt = 0; nt < 4; nt++) {
                uint2 w = *(const uint2*)(Wsh + ((((ks * 4 + si) * 4 + nt) * 32 + lane) << 1));
                mma_f16(acc[0][nt][0], acc[0][nt][1], acc[0][nt][2], acc[0][nt][3],
                        a[si][0].x, a[si][0].y, a[si][0].z, a[si][0].w, w.x, w.y);
                mma_f16(acc[1][nt][0], acc[1][nt][1], acc[1][nt][2], acc[1][nt][3],
                        a[si][1].x, a[si][1].y, a[si][1].z, a[si][1].w, w.x, w.y);
            }
        }

        // store K-partials to Rsh
        #pragma unroll
        for (int mt = 0; mt < 2; mt++) {
            #pragma unroll
            for (int nt = 0; nt < 4; nt++) {
                int row = mt * 16 + g;
                int col = nt * 8 + 2 * t;
                *(float2*)(Rsh + (ks * 32 + row) * RSTR + col) =
                    make_float2(acc[mt][nt][0], acc[mt][nt][1]);
                *(float2*)(Rsh + (ks * 32 + row + 8) * RSTR + col) =
                    make_float2(acc[mt][nt][2], acc[mt][nt][3]);
            }
        }
        __syncthreads();

        // 16-way reduce + LSTM cell (256 active threads)
        if (tid < 256) {
            float s0 = xv0, s1 = xv1, s2 = xv2, s3 = xv3;
            #pragma unroll
            for (int kk = 0; kk < 16; kk++) {
                const float* rp = Rsh + (kk * 32 + eb) * RSTR + ej;
                s0 += rp[0];
                s1 += rp[8];
                s2 += rp[16];
                s3 += rp[24];
            }
            float iv = sigm(s0);
            float fv = sigm(s1);
            float gv = tanhf(s2);
            float ov = sigm(s3);
            c_state = fv * c_state + iv * gv;
            float hval = ov * tanhf(c_state);

            // publish h (fp16, frag-permuted): pair adjacent cols into one u32
            unsigned hbits = (unsigned)__half_as_ushort(__float2half_rn(hval));
            unsigned obits = __shfl_xor_sync(0xffffffffu, hbits, 1);
            if ((ej & 1) == 0) {
                unsigned packed = (hbits & 0xffffu) | (obits << 16);
                g_hH[1 - p][foff] = packed;
            }
            outseq[mrow * H_ + hcol] = hval + rv;   // fp32 output (+residual)
        }

        phase++;
        grid_barrier(phase);
        p ^= 1;
    }
}

// ---------------- launch ----------------
extern "C" void kernel_launch(void* const* d_in, const int* in_sizes, int n_in,
                              void* d_out, int out_size) {
    const float* x    = (const float*)d_in[0];
    const float* Wih0 = (const float*)d_in[1];
    const float* Whh0 = (const float*)d_in[2];
    const float* bih0 = (const float*)d_in[3];
    const float* bhh0 = (const float*)d_in[4];
    const float* Wih1 = (const float*)d_in[5];
    const float* Whh1 = (const float*)d_in[6];
    const float* bih1 = (const float*)d_in[7];
    const float* bhh1 = (const float*)d_in[8];
    float* out = (float*)d_out;

    cudaFuncSetAttribute(lstm_scan_kernel,
                         cudaFuncAttributeMaxDynamicSharedMemorySize, SCAN_SMEM);

    void* p;
    cudaGetSymbolAddress(&p, g_xg);     float* xg = (float*)p;
    cudaGetSymbolAddress(&p, g_h0seq);  float* h0 = (float*)p;
    cudaGetSymbolAddress(&p, g_arrive); unsigned* arr = (unsigned*)p;

    dim3 gg(32, 128);  // (N tiles, M tiles)

    // layer 0
    cudaMemsetAsync(arr, 0, sizeof(unsigned) * NCNT * CSTR);
    gemm_xg_kernel<<<gg, 256>>>(x, Wih0, bih0, bhh0, xg);
    lstm_scan_kernel<<<NBLK, NTHR, SCAN_SMEM>>>(xg, Whh0, nullptr, h0);
    // layer 1 (+ residual into final out)
    cudaMemsetAsync(arr, 0, sizeof(unsigned) * NCNT * CSTR);
    gemm_xg_kernel<<<gg, 256>>>(h0, Wih1, bih1, bhh1, xg);
    lstm_scan_kernel<<<NBLK, NTHR, SCAN_SMEM>>>(xg, Whh1, h0, out);
}

// round 7
// speedup vs baseline: 1.4159x; 1.0364x over previous
#include <cuda_runtime.h>
#include <cuda_fp16.h>
#include <cstdint>

#define B_  32
#define T_  512
#define H_  1024
#define G4_ 4096
#define M_  (B_ * T_)   // 16384
#define NBLK 128
#define NTHR 512
#define NCNT 16          // striped barrier counters
#define CSTR 64          // counter stride in u32 (256 B -> distinct LTS slices)
#define BLKS_PER_CNT (NBLK / NCNT)

// ---------------- static device scratch (no allocations allowed) ----------------
__device__ float g_xg[(size_t)M_ * G4_];     // gate preactivations for current layer
__device__ float g_h0seq[(size_t)M_ * H_];   // layer-0 output sequence (normal layout)
// frag-permuted recurrent h (fp16, packed half2), double buffered
__device__ unsigned g_hH[2][16384];          // 64 KB per buffer
__device__ unsigned g_arrive[NCNT * CSTR];   // striped monotonic counters

// ---------------- helpers ----------------
__device__ __forceinline__ void mma_f16(float& c0, float& c1, float& c2, float& c3,
                                        uint32_t a0, uint32_t a1, uint32_t a2, uint32_t a3,
                                        uint32_t b0, uint32_t b1) {
    asm volatile(
        "mma.sync.aligned.m16n8k16.row.col.f32.f16.f16.f32 "
        "{%0,%1,%2,%3},{%4,%5,%6,%7},{%8,%9},{%0,%1,%2,%3};"
        : "+f"(c0), "+f"(c1), "+f"(c2), "+f"(c3)
        : "r"(a0), "r"(a1), "r"(a2), "r"(a3), "r"(b0), "r"(b1));
}

__device__ __forceinline__ float sigm(float x) {
    return 1.0f / (1.0f + __expf(-x));
}

__device__ __forceinline__ unsigned pack_h2(float a, float b) {
    __half2 h = __floats2half2_rn(a, b);
    return *(unsigned*)&h;
}

// striped release/acquire grid barrier: 16 counters, 8 blocks each (monotonic)
__device__ __forceinline__ void grid_barrier(unsigned phase) {
    __syncthreads();
    if (threadIdx.x == 0) {
        asm volatile("red.release.gpu.global.add.u32 [%0], 1;"
                     :: "l"(&g_arrive[(blockIdx.x & (NCNT - 1)) * CSTR]) : "memory");
    }
    if (threadIdx.x < NCNT) {
        const unsigned target = phase * BLKS_PER_CNT;
        const unsigned* cp = &g_arrive[threadIdx.x * CSTR];
        unsigned v;
        do {
            asm volatile("ld.acquire.gpu.global.u32 %0, [%1];"
                         : "=r"(v) : "l"(cp) : "memory");
        } while (v < target);
    }
    __syncthreads();
}

// ---------------- big GEMM (fp16 mma): C[M,4096] = A[M,1024] * W[4096,1024]^T + bias ----
// CTA tile 128x128, K-chunk 16 (one k16 mma step), 8 warps (2M x 4N), warp tile 64x32.
// Global fp32 -> half2 at smem fill. Smem row = 8 u32 + pad4 = 12 u32 (conflict-free:
// g*12+t mod 32 distinct across the 8 quads). LDG for next chunk issued under mma.
#define GS_ 12

__global__ __launch_bounds__(256, 2)
void gemm_xg_kernel(const float* __restrict__ A,
                    const float* __restrict__ W,
                    const float* __restrict__ b0,
                    const float* __restrict__ b1,
                    float* __restrict__ C)
{
    __shared__ unsigned Ash[128 * GS_];
    __shared__ unsigned Bsh[128 * GS_];

    const int tid  = threadIdx.x;
    const int wid  = tid >> 5, lane = tid & 31;
    const int g    = lane >> 2, t = lane & 3;
    const int wm   = wid & 1, wn = wid >> 1;
    const int cm   = blockIdx.y * 128;
    const int cn   = blockIdx.x * 128;

    float acc[4][4][4];
    #pragma unroll
    for (int i = 0; i < 4; i++)
        #pragma unroll
        for (int j = 0; j < 4; j++)
            #pragma unroll
            for (int q = 0; q < 4; q++) acc[i][j][q] = 0.0f;

    const int r0 = tid >> 1;          // 0..127 (row within tile)
    const int q0 = tid & 1;           // which 8-float segment of the 16-wide chunk

    const float* Ag = A + (size_t)(cm + r0) * 1024 + 8 * q0;
    const float* Bg = W + (size_t)(cn + r0) * 1024 + 8 * q0;

    float4 av0 = *(const float4*)(Ag);
    float4 av1 = *(const float4*)(Ag + 4);
    float4 bv0 = *(const float4*)(Bg);
    float4 bv1 = *(const float4*)(Bg + 4);

    for (int kk = 0; kk < 1024; kk += 16) {
        __syncthreads();   // previous iteration's mma done reading smem
        {
            uint4 pa, pb;
            pa.x = pack_h2(av0.x, av0.y); pa.y = pack_h2(av0.z, av0.w);
            pa.z = pack_h2(av1.x, av1.y); pa.w = pack_h2(av1.z, av1.w);
            pb.x = pack_h2(bv0.x, bv0.y); pb.y = pack_h2(bv0.z, bv0.w);
            pb.z = pack_h2(bv1.x, bv1.y); pb.w = pack_h2(bv1.z, bv1.w);
            *(uint4*)(Ash + r0 * GS_ + 4 * q0) = pa;
            *(uint4*)(Bsh + r0 * GS_ + 4 * q0) = pb;
        }
        __syncthreads();

        if (kk + 16 < 1024) {     // prefetch next chunk under the mma work
            av0 = *(const float4*)(Ag + kk + 16);
            av1 = *(const float4*)(Ag + kk + 20);
            bv0 = *(const float4*)(Bg + kk + 16);
            bv1 = *(const float4*)(Bg + kk + 20);
        }

        uint32_t af[4][4];
        uint32_t bf[4][2];
        #pragma unroll
        for (int mt = 0; mt < 4; mt++) {
            int rb = wm * 64 + mt * 16;
            af[mt][0] = Ash[(rb + g)     * GS_ + t];
            af[mt][1] = Ash[(rb + g + 8) * GS_ + t];
            af[mt][2] = Ash[(rb + g)     * GS_ + t + 4];
            af[mt][3] = Ash[(rb + g + 8) * GS_ + t + 4];
        }
        #pragma unroll
        for (int nt = 0; nt < 4; nt++) {
            int nb = wn * 32 + nt * 8 + g;
            bf[nt][0] = Bsh[nb * GS_ + t];
            bf[nt][1] = Bsh[nb * GS_ + t + 4];
        }
        #pragma unroll
        for (int mt = 0; mt < 4; mt++)
            #pragma unroll
            for (int nt = 0; nt < 4; nt++)
                mma_f16(acc[mt][nt][0], acc[mt][nt][1], acc[mt][nt][2], acc[mt][nt][3],
                        af[mt][0], af[mt][1], af[mt][2], af[mt][3],
                        bf[nt][0], bf[nt][1]);
    }

    // epilogue: add bias, write fp32
    #pragma unroll
    for (int mt = 0; mt < 4; mt++) {
        #pragma unroll
        for (int nt = 0; nt < 4; nt++) {
            int m = cm + wm * 64 + mt * 16 + g;
            int n = cn + wn * 32 + nt * 8 + 2 * t;
            float bs0 = b0[n] + b1[n];
            float bs1 = b0[n + 1] + b1[n + 1];
            float2 v0 = make_float2(acc[mt][nt][0] + bs0, acc[mt][nt][1] + bs1);
            float2 v1 = make_float2(acc[mt][nt][2] + bs0, acc[mt][nt][3] + bs1);
            *(float2*)(C + (size_t)m * G4_ + n) = v0;
            *(float2*)(C + (size_t)(m + 8) * G4_ + n) = v1;
        }
    }
}

// ---------------- persistent LSTM scan (fp16 recurrent mma, striped barrier) ----------------
// (unchanged from round 6 — control for this round's GEMM attribution experiment)
#define WS_  16384                 // W frag u32s: 16ks*4si*4nt*32lane*2
#define RSTR 40
#define RS_  (16 * 32 * RSTR)      // reduction buffer floats
#define SCAN_SMEM (WS_ * 4 + RS_ * 4)   // 147456 B

__global__ __launch_bounds__(NTHR, 1)
void lstm_scan_kernel(const float* __restrict__ xg,     // [M, 4096]
                      const float* __restrict__ Whh,    // [4096, 1024]
                      const float* __restrict__ resid,  // [M, 1024] or nullptr
                      float* __restrict__ outseq)       // [M, 1024]
{
    extern __shared__ float sm[];
    unsigned* Wsh = (unsigned*)sm;        // WS_ u32
    float*    Rsh = sm + WS_;             // RS_ floats

    const int tid  = threadIdx.x;
    const int bid  = blockIdx.x;
    const int wid  = tid >> 5, lane = tid & 31;
    const int g    = lane >> 2, t = lane & 3;
    const int ks   = wid;                 // 0..15, K-slice of 64

    // ---- fill W frags (fp16 packed half2), frag-permuted for m16n8k16 ----
    for (int e = tid; e < WS_; e += NTHR) {
        int rr = e & 1;
        int ln = (e >> 1) & 31;
        int nt = (e >> 6) & 3;
        int si = (e >> 8) & 3;
        int kk = e >> 10;
        int gg = ln >> 2, tt = ln & 3;
        int n32  = nt * 8 + gg;                              // 0..31 local gate-col
        int wrow = (n32 >> 3) * 1024 + bid * 8 + (n32 & 7);  // Whh row (gate-major)
        int k0   = kk * 64 + si * 16 + 2 * tt + rr * 8;
        Wsh[e] = pack_h2(Whh[(size_t)wrow * 1024 + k0],
                         Whh[(size_t)wrow * 1024 + k0 + 1]);
    }

    // elementwise ownership (tid < 256): (batch eb, local col ej)
    const int eb   = tid >> 3;
    const int ej   = tid & 7;
    const int hcol = bid * 8 + ej;
    const int c_   = bid >> 1;
    const int fmt  = eb >> 4;
    const int ridx = (bid & 1) * 2 + ((eb >> 3) & 1);
    const int foff = (((c_ * 2 + fmt) * 32) + (eb & 7) * 4 + (ej >> 1)) * 4 + ridx;

    // init h(0) = 0 in buf0
    if (tid < 256 && (ej & 1) == 0) g_hH[0][foff] = 0u;
    float c_state = 0.0f;

    unsigned phase = 1;
    grid_barrier(phase);

    int p = 0;
    for (int ts = 0; ts < T_; ts++) {
        // prefetch xg + residual (independent of h; overlaps barrier/loads)
        float xv0 = 0.f, xv1 = 0.f, xv2 = 0.f, xv3 = 0.f, rv = 0.f;
        size_t mrow = 0;
        if (tid < 256) {
            mrow = (size_t)eb * T_ + ts;
            const float* xp = xg + mrow * G4_ + hcol;
            xv0 = __ldcs(xp);
            xv1 = __ldcs(xp + 1024);
            xv2 = __ldcs(xp + 2048);
            xv3 = __ldcs(xp + 3072);
            if (resid) rv = __ldcs(resid + mrow * H_ + hcol);
        }

        // ---- batched A loads (8x LDG.128) for maximum MLP ----
        const uint4* hA = (const uint4*)g_hH[p];
        uint4 a[4][2];
        #pragma unroll
        for (int si = 0; si < 4; si++) {
            int c = ks * 4 + si;
            a[si][0] = __ldcg(hA + (c * 2 + 0) * 32 + lane);
            a[si][1] = __ldcg(hA + (c * 2 + 1) * 32 + lane);
        }

        float acc[2][4][4];
        #pragma unroll
        for (int mt = 0; mt < 2; mt++)
            #pragma unroll
            for (int nt = 0; nt < 4; nt++)
                #pragma unroll
                for (int q = 0; q < 4; q++) acc[mt][nt][q] = 0.0f;

        #pragma unroll
        for (int si = 0; si < 4; si++) {
            #pragma unroll
            for (int nt = 0; nt < 4; nt++) {
                uint2 w = *(const uint2*)(Wsh + ((((ks * 4 + si) * 4 + nt) * 32 + lane) << 1));
                mma_f16(acc[0][nt][0], acc[0][nt][1], acc[0][nt][2], acc[0][nt][3],
                        a[si][0].x, a[si][0].y, a[si][0].z, a[si][0].w, w.x, w.y);
                mma_f16(acc[1][nt][0], acc[1][nt][1], acc[1][nt][2], acc[1][nt][3],
                        a[si][1].x, a[si][1].y, a[si][1].z, a[si][1].w, w.x, w.y);
            }
        }

        // store K-partials to Rsh
        #pragma unroll
        for (int mt = 0; mt < 2; mt++) {
            #pragma unroll
            for (int nt = 0; nt < 4; nt++) {
                int row = mt * 16 + g;
                int col = nt * 8 + 2 * t;
                *(float2*)(Rsh + (ks * 32 + row) * RSTR + col) =
                    make_float2(acc[mt][nt][0], acc[mt][nt][1]);
                *(float2*)(Rsh + (ks * 32 + row + 8) * RSTR + col) =
                    make_float2(acc[mt][nt][2], acc[mt][nt][3]);
            }
        }
        __syncthreads();

        // 16-way reduce + LSTM cell (256 active threads)
        if (tid < 256) {
            float s0 = xv0, s1 = xv1, s2 = xv2, s3 = xv3;
            #pragma unroll
            for (int kk = 0; kk < 16; kk++) {
                const float* rp = Rsh + (kk * 32 + eb) * RSTR + ej;
                s0 += rp[0];
                s1 += rp[8];
                s2 += rp[16];
                s3 += rp[24];
            }
            float iv = sigm(s0);
            float fv = sigm(s1);
            float gv = tanhf(s2);
            float ov = sigm(s3);
            c_state = fv * c_state + iv * gv;
            float hval = ov * tanhf(c_state);

            // publish h (fp16, frag-permuted): pair adjacent cols into one u32
            unsigned hbits = (unsigned)__half_as_ushort(__float2half_rn(hval));
            unsigned obits = __shfl_xor_sync(0xffffffffu, hbits, 1);
            if ((ej & 1) == 0) {
                unsigned packed = (hbits & 0xffffu) | (obits << 16);
                g_hH[1 - p][foff] = packed;
            }
            outseq[mrow * H_ + hcol] = hval + rv;   // fp32 output (+residual)
        }

        phase++;
        grid_barrier(phase);
        p ^= 1;
    }
}

// ---------------- launch ----------------
extern "C" void kernel_launch(void* const* d_in, const int* in_sizes, int n_in,
                              void* d_out, int out_size) {
    const float* x    = (const float*)d_in[0];
    const float* Wih0 = (const float*)d_in[1];
    const float* Whh0 = (const float*)d_in[2];
    const float* bih0 = (const float*)d_in[3];
    const float* bhh0 = (const float*)d_in[4];
    const float* Wih1 = (const float*)d_in[5];
    const float* Whh1 = (const float*)d_in[6];
    const float* bih1 = (const float*)d_in[7];
    const float* bhh1 = (const float*)d_in[8];
    float* out = (float*)d_out;

    cudaFuncSetAttribute(lstm_scan_kernel,
                         cudaFuncAttributeMaxDynamicSharedMemorySize, SCAN_SMEM);

    void* p;
    cudaGetSymbolAddress(&p, g_xg);     float* xg = (float*)p;
    cudaGetSymbolAddress(&p, g_h0seq);  float* h0 = (float*)p;
    cudaGetSymbolAddress(&p, g_arrive); unsigned* arr = (unsigned*)p;

    dim3 gg(32, 128);  // (N tiles, M tiles)

    // layer 0
    cudaMemsetAsync(arr, 0, sizeof(unsigned) * NCNT * CSTR);
    gemm_xg_kernel<<<gg, 256>>>(x, Wih0, bih0, bhh0, xg);
    lstm_scan_kernel<<<NBLK, NTHR, SCAN_SMEM>>>(xg, Whh0, nullptr, h0);
    // layer 1 (+ residual into final out)
    cudaMemsetAsync(arr, 0, sizeof(unsigned) * NCNT * CSTR);
    gemm_xg_kernel<<<gg, 256>>>(h0, Wih1, bih1, bhh1, xg);
    lstm_scan_kernel<<<NBLK, NTHR, SCAN_SMEM>>>(xg, Whh1, h0, out);
}

// round 8
// speedup vs baseline: 1.7658x; 1.2471x over previous
#include <cuda_runtime.h>
#include <cuda_fp16.h>
#include <cstdint>

#define B_  32
#define T_  512
#define H_  1024
#define G4_ 4096
#define M_  (B_ * T_)   // 16384
#define NBLK 128
#define NTHR 512
#define NCNT 16
#define CSTR 64
#define BLKS_PER_CNT (NBLK / NCNT)

// ---------------- static device scratch ----------------
__device__ float g_xg[(size_t)M_ * G4_];     // layer-0 gate preactivations (from GEMM0)
// frag-permuted fp16 h buffers, double buffered by step parity
__device__ unsigned g_h0H[2][16384];         // 64 KB each
__device__ unsigned g_h1H[2][16384];
__device__ unsigned g_arrive[NCNT * CSTR];

// ---------------- helpers ----------------
__device__ __forceinline__ void mma_f16(float& c0, float& c1, float& c2, float& c3,
                                        uint32_t a0, uint32_t a1, uint32_t a2, uint32_t a3,
                                        uint32_t b0, uint32_t b1) {
    asm volatile(
        "mma.sync.aligned.m16n8k16.row.col.f32.f16.f16.f32 "
        "{%0,%1,%2,%3},{%4,%5,%6,%7},{%8,%9},{%0,%1,%2,%3};"
        : "+f"(c0), "+f"(c1), "+f"(c2), "+f"(c3)
        : "r"(a0), "r"(a1), "r"(a2), "r"(a3), "r"(b0), "r"(b1));
}

__device__ __forceinline__ float sigm(float x) { return 1.0f / (1.0f + __expf(-x)); }

__device__ __forceinline__ unsigned pack_h2(float a, float b) {
    __half2 h = __floats2half2_rn(a, b);
    return *(unsigned*)&h;
}

__device__ __forceinline__ void barn(int id, int cnt) {
    asm volatile("bar.sync %0, %1;" :: "r"(id), "r"(cnt) : "memory");
}

__device__ __forceinline__ void grid_barrier(unsigned phase) {
    __syncthreads();
    if (threadIdx.x == 0) {
        asm volatile("red.release.gpu.global.add.u32 [%0], 1;"
                     :: "l"(&g_arrive[(blockIdx.x & (NCNT - 1)) * CSTR]) : "memory");
    }
    if (threadIdx.x < NCNT) {
        const unsigned target = phase * BLKS_PER_CNT;
        const unsigned* cp = &g_arrive[threadIdx.x * CSTR];
        unsigned v;
        do {
            asm volatile("ld.acquire.gpu.global.u32 %0, [%1];"
                         : "=r"(v) : "l"(cp) : "memory");
        } while (v < target);
    }
    __syncthreads();
}

// ---------------- big GEMM (fp16 mma): C[M,4096] = A[M,1024]*W^T + bias ----------------
#define GS_ 12

__global__ __launch_bounds__(256, 2)
void gemm_xg_kernel(const float* __restrict__ A,
                    const float* __restrict__ W,
                    const float* __restrict__ b0,
                    const float* __restrict__ b1,
                    float* __restrict__ C)
{
    __shared__ unsigned Ash[128 * GS_];
    __shared__ unsigned Bsh[128 * GS_];

    const int tid  = threadIdx.x;
    const int wid  = tid >> 5, lane = tid & 31;
    const int g    = lane >> 2, t = lane & 3;
    const int wm   = wid & 1, wn = wid >> 1;
    const int cm   = blockIdx.y * 128;
    const int cn   = blockIdx.x * 128;

    float acc[4][4][4];
    #pragma unroll
    for (int i = 0; i < 4; i++)
        #pragma unroll
        for (int j = 0; j < 4; j++)
            #pragma unroll
            for (int q = 0; q < 4; q++) acc[i][j][q] = 0.0f;

    const int r0 = tid >> 1;
    const int q0 = tid & 1;

    const float* Ag = A + (size_t)(cm + r0) * 1024 + 8 * q0;
    const float* Bg = W + (size_t)(cn + r0) * 1024 + 8 * q0;

    float4 av0 = *(const float4*)(Ag);
    float4 av1 = *(const float4*)(Ag + 4);
    float4 bv0 = *(const float4*)(Bg);
    float4 bv1 = *(const float4*)(Bg + 4);

    for (int kk = 0; kk < 1024; kk += 16) {
        __syncthreads();
        {
            uint4 pa, pb;
            pa.x = pack_h2(av0.x, av0.y); pa.y = pack_h2(av0.z, av0.w);
            pa.z = pack_h2(av1.x, av1.y); pa.w = pack_h2(av1.z, av1.w);
            pb.x = pack_h2(bv0.x, bv0.y); pb.y = pack_h2(bv0.z, bv0.w);
            pb.z = pack_h2(bv1.x, bv1.y); pb.w = pack_h2(bv1.z, bv1.w);
            *(uint4*)(Ash + r0 * GS_ + 4 * q0) = pa;
            *(uint4*)(Bsh + r0 * GS_ + 4 * q0) = pb;
        }
        __syncthreads();

        if (kk + 16 < 1024) {
            av0 = *(const float4*)(Ag + kk + 16);
            av1 = *(const float4*)(Ag + kk + 20);
            bv0 = *(const float4*)(Bg + kk + 16);
            bv1 = *(const float4*)(Bg + kk + 20);
        }

        uint32_t af[4][4];
        uint32_t bf[4][2];
        #pragma unroll
        for (int mt = 0; mt < 4; mt++) {
            int rb = wm * 64 + mt * 16;
            af[mt][0] = Ash[(rb + g)     * GS_ + t];
            af[mt][1] = Ash[(rb + g + 8) * GS_ + t];
            af[mt][2] = Ash[(rb + g)     * GS_ + t + 4];
            af[mt][3] = Ash[(rb + g + 8) * GS_ + t + 4];
        }
        #pragma unroll
        for (int nt = 0; nt < 4; nt++) {
            int nb = wn * 32 + nt * 8 + g;
            bf[nt][0] = Bsh[nb * GS_ + t];
            bf[nt][1] = Bsh[nb * GS_ + t + 4];
        }
        #pragma unroll
        for (int mt = 0; mt < 4; mt++)
            #pragma unroll
            for (int nt = 0; nt < 4; nt++)
                mma_f16(acc[mt][nt][0], acc[mt][nt][1], acc[mt][nt][2], acc[mt][nt][3],
                        af[mt][0], af[mt][1], af[mt][2], af[mt][3],
                        bf[nt][0], bf[nt][1]);
    }

    #pragma unroll
    for (int mt = 0; mt < 4; mt++) {
        #pragma unroll
        for (int nt = 0; nt < 4; nt++) {
            int m = cm + wm * 64 + mt * 16 + g;
            int n = cn + wn * 32 + nt * 8 + 2 * t;
            float bs0 = b0[n] + b1[n];
            float bs1 = b0[n + 1] + b1[n + 1];
            float2 v0 = make_float2(acc[mt][nt][0] + bs0, acc[mt][nt][1] + bs1);
            float2 v1 = make_float2(acc[mt][nt][2] + bs0, acc[mt][nt][3] + bs1);
            *(float2*)(C + (size_t)m * G4_ + n) = v0;
            *(float2*)(C + (size_t)(m + 8) * G4_ + n) = v1;
        }
    }
}

// ---------------- fused two-layer persistent LSTM scan ----------------
// Round r (0..512): warps 0-7 compute layer-0 step r (K=1024 vs h0^{r-1});
// warps 8-15 compute layer-1 step r-1 as one K=2048 GEMM vs [h0^{r-1}; h1^{r-2}].
// Shared 34KB reduce buffer sequenced via named barriers 1/2/3.
#define WA_ 16384                       // Whh0 frag u32s
#define WB_ 32768                       // [Wih1|Whh1] frag u32s
#define RSTR 34
#define RS_ (8 * 32 * RSTR)             // 8704 floats
#define FUSED_SMEM ((WA_ + WB_) * 4 + RS_ * 4)   // 231424 B

__global__ __launch_bounds__(NTHR, 1)
void lstm_fused_kernel(const float* __restrict__ xg,
                       const float* __restrict__ Whh0,
                       const float* __restrict__ Wih1,
                       const float* __restrict__ Whh1,
                       const float* __restrict__ bih1,
                       const float* __restrict__ bhh1,
                       float* __restrict__ outseq)
{
    extern __shared__ unsigned smu[];
    unsigned* WshA = smu;                 // 64 KB
    unsigned* WshB = smu + WA_;           // 128 KB
    float*    Rsh  = (float*)(smu + WA_ + WB_);

    const int tid  = threadIdx.x;
    const int bid  = blockIdx.x;
    const int wid  = tid >> 5, lane = tid & 31;
    const int g    = lane >> 2, t = lane & 3;

    // ---- fill Whh0 frags: ((kq*8+si)*4+nt)*64 + lane*2 + rr ----
    for (int e = tid; e < WA_; e += NTHR) {
        int rr = e & 1;
        int ln = (e >> 1) & 31;
        int nt = (e >> 6) & 3;
        int si = (e >> 8) & 7;
        int kq = e >> 11;
        int n8 = ln >> 2, tt = ln & 3;
        int row = nt * 1024 + bid * 8 + n8;
        int k0  = kq * 128 + si * 16 + 2 * tt + rr * 8;
        WshA[e] = pack_h2(Whh0[(size_t)row * 1024 + k0],
                          Whh0[(size_t)row * 1024 + k0 + 1]);
    }
    // ---- fill [Wih1|Whh1] frags: ((kq*16+si)*4+nt)*64 + lane*2 + rr, K=2048 ----
    for (int e = tid; e < WB_; e += NTHR) {
        int rr = e & 1;
        int ln = (e >> 1) & 31;
        int nt = (e >> 6) & 3;
        int si = (e >> 8) & 15;
        int kq = e >> 12;
        int n8 = ln >> 2, tt = ln & 3;
        int row = nt * 1024 + bid * 8 + n8;
        int kg  = kq * 256 + si * 16 + 2 * tt + rr * 8;
        const float* src = (kg < 1024) ? (Wih1 + (size_t)row * 1024 + kg)
                                       : (Whh1 + (size_t)row * 1024 + (kg - 1024));
        WshB[e] = pack_h2(src[0], src[1]);
    }

    // elementwise ownership (tid < 256)
    const int eb   = tid >> 3;
    const int ej   = tid & 7;
    const int hcol = bid * 8 + ej;
    const int c_   = bid >> 1;
    const int fmt  = eb >> 4;
    const int ridx = (bid & 1) * 2 + ((eb >> 3) & 1);
    const int foff = (((c_ * 2 + fmt) * 32) + (eb & 7) * 4 + (ej >> 1)) * 4 + ridx;

    float bias1[4];
    if (tid < 256) {
        #pragma unroll
        for (int q = 0; q < 4; q++)
            bias1[q] = bih1[q * 1024 + hcol] + bhh1[q * 1024 + hcol];
        if ((ej & 1) == 0) {          // zero h^{-1} buffers (parity 1)
            g_h0H[1][foff] = 0u;
            g_h1H[1][foff] = 0u;
        }
    }
    float c0_state = 0.0f, c1_state = 0.0f, h0_prev = 0.0f;

    grid_barrier(1);

    for (int r = 0; r <= T_; r++) {
        const bool l0 = (r < T_);
        const bool l1 = (r >= 1);

        if (tid < 256) {
            // ---------- layer-0 critical path (warps 0-7, kq = wid) ----------
            const int kq = wid;
            float xv0 = 0.f, xv1 = 0.f, xv2 = 0.f, xv3 = 0.f;
            float acc[2][4][4];
            #pragma unroll
            for (int mt = 0; mt < 2; mt++)
                #pragma unroll
                for (int nt = 0; nt < 4; nt++)
                    #pragma unroll
                    for (int q = 0; q < 4; q++) acc[mt][nt][q] = 0.0f;

            if (l0) {
                const float* xp = xg + ((size_t)eb * T_ + r) * G4_ + hcol;
                xv0 = __ldcs(xp);
                xv1 = __ldcs(xp + 1024);
                xv2 = __ldcs(xp + 2048);
                xv3 = __ldcs(xp + 3072);

                const uint4* hA = (const uint4*)g_h0H[(r + 1) & 1];
                uint4 a[2][4][2];
                #pragma unroll
                for (int h2 = 0; h2 < 2; h2++)
                    #pragma unroll
                    for (int s = 0; s < 4; s++) {
                        int c = kq * 8 + h2 * 4 + s;
                        a[h2][s][0] = __ldcg(hA + (c * 2 + 0) * 32 + lane);
                        a[h2][s][1] = __ldcg(hA + (c * 2 + 1) * 32 + lane);
                    }
                #pragma unroll
                for (int h2 = 0; h2 < 2; h2++)
                    #pragma unroll
                    for (int s = 0; s < 4; s++) {
                        int si = h2 * 4 + s;
                        #pragma unroll
                        for (int nt = 0; nt < 4; nt++) {
                            uint2 w = *(const uint2*)(WshA + (((kq * 8 + si) * 4 + nt) << 6) + lane * 2);
                            mma_f16(acc[0][nt][0], acc[0][nt][1], acc[0][nt][2], acc[0][nt][3],
                                    a[h2][s][0].x, a[h2][s][0].y, a[h2][s][0].z, a[h2][s][0].w, w.x, w.y);
                            mma_f16(acc[1][nt][0], acc[1][nt][1], acc[1][nt][2], acc[1][nt][3],
                                    a[h2][s][1].x, a[h2][s][1].y, a[h2][s][1].z, a[h2][s][1].w, w.x, w.y);
                        }
                    }
                #pragma unroll
                for (int mt = 0; mt < 2; mt++)
                    #pragma unroll
                    for (int nt = 0; nt < 4; nt++) {
                        int row = mt * 16 + g;
                        int col = nt * 8 + 2 * t;
                        *(float2*)(Rsh + (kq * 32 + row) * RSTR + col) =
                            make_float2(acc[mt][nt][0], acc[mt][nt][1]);
                        *(float2*)(Rsh + (kq * 32 + row + 8) * RSTR + col) =
                            make_float2(acc[mt][nt][2], acc[mt][nt][3]);
                    }
            }
            barn(1, 256);                 // L0 partials ready

            float h0_res = h0_prev;       // h0 of step r-1 (for residual)
            if (l0) {
                float s0 = xv0, s1 = xv1, s2 = xv2, s3 = xv3;
                #pragma unroll
                for (int kk = 0; kk < 8; kk++) {
                    const float* rp = Rsh + (kk * 32 + eb) * RSTR + ej;
                    s0 += rp[0]; s1 += rp[8]; s2 += rp[16]; s3 += rp[24];
                }
                float iv = sigm(s0), fv = sigm(s1), gv = tanhf(s2), ov = sigm(s3);
                c0_state = fv * c0_state + iv * gv;
                float hval = ov * tanhf(c0_state);
                h0_prev = hval;
                unsigned hb = (unsigned)__half_as_ushort(__float2half_rn(hval));
                unsigned ob = __shfl_xor_sync(0xffffffffu, hb, 1);
                if ((ej & 1) == 0)
                    g_h0H[r & 1][foff] = (hb & 0xffffu) | (ob << 16);
            }
            barn(2, 512);                 // Rsh free for L1 stores
            barn(3, 512);                 // L1 partials ready
            if (l1) {
                float s0 = bias1[0], s1 = bias1[1], s2 = bias1[2], s3 = bias1[3];
                #pragma unroll
                for (int kk = 0; kk < 8; kk++) {
                    const float* rp = Rsh + (kk * 32 + eb) * RSTR + ej;
                    s0 += rp[0]; s1 += rp[8]; s2 += rp[16]; s3 += rp[24];
                }
                float iv = sigm(s0), fv = sigm(s1), gv = tanhf(s2), ov = sigm(s3);
                c1_state = fv * c1_state + iv * gv;
                float h1val = ov * tanhf(c1_state);
                unsigned hb = (unsigned)__half_as_ushort(__float2half_rn(h1val));
                unsigned ob = __shfl_xor_sync(0xffffffffu, hb, 1);
                if ((ej & 1) == 0)
                    g_h1H[(r + 1) & 1][foff] = (hb & 0xffffu) | (ob << 16);
                outseq[((size_t)eb * T_ + (r - 1)) * H_ + hcol] = h1val + h0_res;
            }
        } else {
            // ---------- layer-1 bulk GEMM (warps 8-15, kq = wid-8, K=2048) ----------
            const int kq = wid - 8;
            float acc[2][4][4];
            #pragma unroll
            for (int mt = 0; mt < 2; mt++)
                #pragma unroll
                for (int nt = 0; nt < 4; nt++)
                    #pragma unroll
                    for (int q = 0; q < 4; q++) acc[mt][nt][q] = 0.0f;

            if (l1) {
                const uint4* baseA;
                int cb;
                if (kq < 4) { baseA = (const uint4*)g_h0H[(r + 1) & 1]; cb = kq * 16; }
                else        { baseA = (const uint4*)g_h1H[r & 1];       cb = (kq - 4) * 16; }

                uint4 b[2][4][2];
                #pragma unroll
                for (int s = 0; s < 4; s++) {
                    int c = cb + s;
                    b[0][s][0] = __ldcg(baseA + (c * 2 + 0) * 32 + lane);
                    b[0][s][1] = __ldcg(baseA + (c * 2 + 1) * 32 + lane);
                }
                #pragma unroll
                for (int wv = 0; wv < 4; wv++) {
                    int cur = wv & 1;
                    if (wv < 3) {
                        #pragma unroll
                        for (int s = 0; s < 4; s++) {
                            int c = cb + (wv + 1) * 4 + s;
                            b[1 - cur][s][0] = __ldcg(baseA + (c * 2 + 0) * 32 + lane);
                            b[1 - cur][s][1] = __ldcg(baseA + (c * 2 + 1) * 32 + lane);
                        }
                    }
                    #pragma unroll
                    for (int s = 0; s < 4; s++) {
                        int si = wv * 4 + s;
                        #pragma unroll
                        for (int nt = 0; nt < 4; nt++) {
                            uint2 w = *(const uint2*)(WshB + (((kq * 16 + si) * 4 + nt) << 6) + lane * 2);
                            mma_f16(acc[0][nt][0], acc[0][nt][1], acc[0][nt][2], acc[0][nt][3],
                                    b[cur][s][0].x, b[cur][s][0].y, b[cur][s][0].z, b[cur][s][0].w, w.x, w.y);
                            mma_f16(acc[1][nt][0], acc[1][nt][1], acc[1][nt][2], acc[1][nt][3],
                                    b[cur][s][1].x, b[cur][s][1].y, b[cur][s][1].z, b[cur][s][1].w, w.x, w.y);
                        }
                    }
                }
            }
            barn(2, 512);                 // wait: Rsh free (L0 reduce done)
            if (l1) {
                #pragma unroll
                for (int mt = 0; mt < 2; mt++)
                    #pragma unroll
                    for (int nt = 0; nt < 4; nt++) {
                        int row = mt * 16 + g;
                        int col = nt * 8 + 2 * t;
                        *(float2*)(Rsh + (kq * 32 + row) * RSTR + col) =
                            make_float2(acc[mt][nt][0], acc[mt][nt][1]);
                        *(float2*)(Rsh + (kq * 32 + row + 8) * RSTR + col) =
                            make_float2(acc[mt][nt][2], acc[mt][nt][3]);
                    }
            }
            barn(3, 512);                 // L1 partials published
        }

        grid_barrier((unsigned)(r + 2));
    }
}

// ---------------- launch ----------------
extern "C" void kernel_launch(void* const* d_in, const int* in_sizes, int n_in,
                              void* d_out, int out_size) {
    const float* x    = (const float*)d_in[0];
    const float* Wih0 = (const float*)d_in[1];
    const float* Whh0 = (const float*)d_in[2];
    const float* bih0 = (const float*)d_in[3];
    const float* bhh0 = (const float*)d_in[4];
    const float* Wih1 = (const float*)d_in[5];
    const float* Whh1 = (const float*)d_in[6];
    const float* bih1 = (const float*)d_in[7];
    const float* bhh1 = (const float*)d_in[8];
    float* out = (float*)d_out;

    cudaFuncSetAttribute(lstm_fused_kernel,
                         cudaFuncAttributeMaxDynamicSharedMemorySize, FUSED_SMEM);

    void* p;
    cudaGetSymbolAddress(&p, g_xg);     float* xg = (float*)p;
    cudaGetSymbolAddress(&p, g_arrive); unsigned* arr = (unsigned*)p;

    dim3 gg(32, 128);

    cudaMemsetAsync(arr, 0, sizeof(unsigned) * NCNT * CSTR);
    gemm_xg_kernel<<<gg, 256>>>(x, Wih0, bih0, bhh0, xg);
    lstm_fused_kernel<<<NBLK, NTHR, FUSED_SMEM>>>(xg, Whh0, Wih1, Whh1, bih1, bhh1, out);
}

// round 10
// speedup vs baseline: 2.2267x; 1.2610x over previous
#include <cuda_runtime.h>
#include <cuda_fp16.h>
#include <cstdint>

#define B_  32
#define T_  512
#define H_  1024
#define G4_ 4096
#define M_  (B_ * T_)   // 16384
#define NBLK 128
#define NTHR 512
#define NCNT 16
#define CSTR 64
#define BLKS_PER_CNT (NBLK / NCNT)

// ---------------- static device scratch ----------------
__device__ float g_xg[(size_t)M_ * G4_];     // layer-0 gate preactivations (from GEMM0)
__device__ unsigned g_h0H[2][16384];         // frag-permuted fp16 h0, parity-buffered
__device__ unsigned g_h1H[2][16384];
__device__ unsigned g_arrive[NCNT * CSTR];

// ---------------- helpers ----------------
__device__ __forceinline__ void mma_f16(float& c0, float& c1, float& c2, float& c3,
                                        uint32_t a0, uint32_t a1, uint32_t a2, uint32_t a3,
                                        uint32_t b0, uint32_t b1) {
    asm volatile(
        "mma.sync.aligned.m16n8k16.row.col.f32.f16.f16.f32 "
        "{%0,%1,%2,%3},{%4,%5,%6,%7},{%8,%9},{%0,%1,%2,%3};"
        : "+f"(c0), "+f"(c1), "+f"(c2), "+f"(c3)
        : "r"(a0), "r"(a1), "r"(a2), "r"(a3), "r"(b0), "r"(b1));
}

__device__ __forceinline__ float sigm(float x) {
    return __fdividef(1.0f, 1.0f + __expf(-x));
}

__device__ __forceinline__ float fast_tanh(float x) {
    x = fminf(fmaxf(x, -8.0f), 8.0f);
    float e = __expf(2.0f * x);
    return __fdividef(e - 1.0f, e + 1.0f);
}

__device__ __forceinline__ unsigned pack_h2(float a, float b) {
    __half2 h = __floats2half2_rn(a, b);
    return *(unsigned*)&h;
}

__device__ __forceinline__ void barn(int id, int cnt) {
    asm volatile("bar.sync %0, %1;" :: "r"(id), "r"(cnt) : "memory");
}

__device__ __forceinline__ void grid_barrier(unsigned phase) {
    __syncthreads();
    if (threadIdx.x == 0) {
        asm volatile("red.release.gpu.global.add.u32 [%0], 1;"
                     :: "l"(&g_arrive[(blockIdx.x & (NCNT - 1)) * CSTR]) : "memory");
    }
    if (threadIdx.x < NCNT) {
        const unsigned target = phase * BLKS_PER_CNT;
        const unsigned* cp = &g_arrive[threadIdx.x * CSTR];
        unsigned v;
        do {
            asm volatile("ld.acquire.gpu.global.u32 %0, [%1];"
                         : "=r"(v) : "l"(cp) : "memory");
        } while (v < target);
    }
    __syncthreads();
}

// ---------------- big GEMM (fp16 mma): C[M,4096] = A[M,1024]*W^T + bias ----------------
#define GS_ 12

__global__ __launch_bounds__(256, 2)
void gemm_xg_kernel(const float* __restrict__ A,
                    const float* __restrict__ W,
                    const float* __restrict__ b0,
                    const float* __restrict__ b1,
                    float* __restrict__ C)
{
    __shared__ unsigned Ash[128 * GS_];
    __shared__ unsigned Bsh[128 * GS_];

    const int tid  = threadIdx.x;
    const int wid  = tid >> 5, lane = tid & 31;
    const int g    = lane >> 2, t = lane & 3;
    const int wm   = wid & 1, wn = wid >> 1;
    const int cm   = blockIdx.y * 128;
    const int cn   = blockIdx.x * 128;

    float acc[4][4][4];
    #pragma unroll
    for (int i = 0; i < 4; i++)
        #pragma unroll
        for (int j = 0; j < 4; j++)
            #pragma unroll
            for (int q = 0; q < 4; q++) acc[i][j][q] = 0.0f;

    const int r0 = tid >> 1;
    const int q0 = tid & 1;

    const float* Ag = A + (size_t)(cm + r0) * 1024 + 8 * q0;
    const float* Bg = W + (size_t)(cn + r0) * 1024 + 8 * q0;

    float4 av0 = *(const float4*)(Ag);
    float4 av1 = *(const float4*)(Ag + 4);
    float4 bv0 = *(const float4*)(Bg);
    float4 bv1 = *(const float4*)(Bg + 4);

    for (int kk = 0; kk < 1024; kk += 16) {
        __syncthreads();
        {
            uint4 pa, pb;
            pa.x = pack_h2(av0.x, av0.y); pa.y = pack_h2(av0.z, av0.w);
            pa.z = pack_h2(av1.x, av1.y); pa.w = pack_h2(av1.z, av1.w);
            pb.x = pack_h2(bv0.x, bv0.y); pb.y = pack_h2(bv0.z, bv0.w);
            pb.z = pack_h2(bv1.x, bv1.y); pb.w = pack_h2(bv1.z, bv1.w);
            *(uint4*)(Ash + r0 * GS_ + 4 * q0) = pa;
            *(uint4*)(Bsh + r0 * GS_ + 4 * q0) = pb;
        }
        __syncthreads();

        if (kk + 16 < 1024) {
            av0 = *(const float4*)(Ag + kk + 16);
            av1 = *(const float4*)(Ag + kk + 20);
            bv0 = *(const float4*)(Bg + kk + 16);
            bv1 = *(const float4*)(Bg + kk + 20);
        }

        uint32_t af[4][4];
        uint32_t bf[4][2];
        #pragma unroll
        for (int mt = 0; mt < 4; mt++) {
            int rb = wm * 64 + mt * 16;
            af[mt][0] = Ash[(rb + g)     * GS_ + t];
            af[mt][1] = Ash[(rb + g + 8) * GS_ + t];
            af[mt][2] = Ash[(rb + g)     * GS_ + t + 4];
            af[mt][3] = Ash[(rb + g + 8) * GS_ + t + 4];
        }
        #pragma unroll
        for (int nt = 0; nt < 4; nt++) {
            int nb = wn * 32 + nt * 8 + g;
            bf[nt][0] = Bsh[nb * GS_ + t];
            bf[nt][1] = Bsh[nb * GS_ + t + 4];
        }
        #pragma unroll
        for (int mt = 0; mt < 4; mt++)
            #pragma unroll
            for (int nt = 0; nt < 4; nt++)
                mma_f16(acc[mt][nt][0], acc[mt][nt][1], acc[mt][nt][2], acc[mt][nt][3],
                        af[mt][0], af[mt][1], af[mt][2], af[mt][3],
                        bf[nt][0], bf[nt][1]);
    }

    #pragma unroll
    for (int mt = 0; mt < 4; mt++) {
        #pragma unroll
        for (int nt = 0; nt < 4; nt++) {
            int m = cm + wm * 64 + mt * 16 + g;
            int n = cn + wn * 32 + nt * 8 + 2 * t;
            float bs0 = b0[n] + b1[n];
            float bs1 = b0[n + 1] + b1[n + 1];
            float2 v0 = make_float2(acc[mt][nt][0] + bs0, acc[mt][nt][1] + bs1);
            float2 v1 = make_float2(acc[mt][nt][2] + bs0, acc[mt][nt][3] + bs1);
            *(float2*)(C + (size_t)m * G4_ + n) = v0;
            *(float2*)(C + (size_t)(m + 8) * G4_ + n) = v1;
        }
    }
}

// ---------------- fused two-layer scan, parallel L0/L1 tails ----------------
// smem (u32): WshA[16384] WshB[32768] RshA[4352] RshB[4352] hbuf[256(half x512)]
#define WA_  16384
#define WB_  32768
#define RPK  17                         // packed reduce row stride (u32)
#define RPKS (8 * 32 * RPK)             // 4352 u32 per buffer
#define FUSED_SMEM ((WA_ + WB_ + 2 * RPKS + 256) * 4)   // 232448 B

__global__ __launch_bounds__(NTHR, 1)
void lstm_fused_kernel(const float* __restrict__ xg,
                       const float* __restrict__ Whh0,
                       const float* __restrict__ Wih1,
                       const float* __restrict__ Whh1,
                       const float* __restrict__ bih1,
                       const float* __restrict__ bhh1,
                       float* __restrict__ outseq)
{
    extern __shared__ unsigned smu[];
    unsigned* WshA = smu;
    unsigned* WshB = smu + WA_;
    unsigned* RshA = smu + WA_ + WB_;
    unsigned* RshB = RshA + RPKS;
    __half*   hbuf = (__half*)(RshB + RPKS);    // [2][256]

    const int tid  = threadIdx.x;
    const int bid  = blockIdx.x;
    const int wid  = tid >> 5, lane = tid & 31;
    const int g    = lane >> 2, t = lane & 3;

    // ---- fill Whh0 frags ----
    for (int e = tid; e < WA_; e += NTHR) {
        int rr = e & 1;
        int ln = (e >> 1) & 31;
        int nt = (e >> 6) & 3;
        int si = (e >> 8) & 7;
        int kq = e >> 11;
        int n8 = ln >> 2, tt = ln & 3;
        int row = nt * 1024 + bid * 8 + n8;
        int k0  = kq * 128 + si * 16 + 2 * tt + rr * 8;
        WshA[e] = pack_h2(Whh0[(size_t)row * 1024 + k0],
                          Whh0[(size_t)row * 1024 + k0 + 1]);
    }
    // ---- fill [Wih1|Whh1] frags (K=2048) ----
    for (int e = tid; e < WB_; e += NTHR) {
        int rr = e & 1;
        int ln = (e >> 1) & 31;
        int nt = (e >> 6) & 3;
        int si = (e >> 8) & 15;
        int kq = e >> 12;
        int n8 = ln >> 2, tt = ln & 3;
        int row = nt * 1024 + bid * 8 + n8;
        int kg  = kq * 256 + si * 16 + 2 * tt + rr * 8;
        const float* src = (kg < 1024) ? (Wih1 + (size_t)row * 1024 + kg)
                                       : (Whh1 + (size_t)row * 1024 + (kg - 1024));
        WshB[e] = pack_h2(src[0], src[1]);
    }

    // cell mapping (both halves use their low-8-bit id)
    const int cix  = tid & 255;               // cell index 0..255
    const int eb   = cix >> 3;
    const int ej   = cix & 7;
    const int hcol = bid * 8 + ej;
    const int c_   = bid >> 1;
    const int fmt  = eb >> 4;
    const int ridx = (bid & 1) * 2 + ((eb >> 3) & 1);
    const int foff = (((c_ * 2 + fmt) * 32) + (eb & 7) * 4 + (ej >> 1)) * 4 + ridx;

    float c0_state = 0.0f, c1_state = 0.0f;
    float bias1[4];
    if (tid < 256) {
        if ((ej & 1) == 0) g_h0H[1][foff] = 0u;      // h0[-1] = 0
    } else {
        #pragma unroll
        for (int q = 0; q < 4; q++)
            bias1[q] = bih1[q * 1024 + hcol] + bhh1[q * 1024 + hcol];
        if ((ej & 1) == 0) g_h1H[1][foff] = 0u;      // h1[-1] = 0
    }

    grid_barrier(1);

    for (int r = 0; r <= T_; r++) {
        const bool l0 = (r < T_);
        const bool l1 = (r >= 1);

        if (tid < 256) {
            // ============ layer-0 chain (warps 0-7) ============
            const int kq = wid;
            float xv0 = 0.f, xv1 = 0.f, xv2 = 0.f, xv3 = 0.f;
            if (l0) {
                const float* xp = xg + ((size_t)eb * T_ + r) * G4_ + hcol;
                xv0 = __ldcs(xp);
                xv1 = __ldcs(xp + 1024);
                xv2 = __ldcs(xp + 2048);
                xv3 = __ldcs(xp + 3072);

                float acc[2][4][4];
                #pragma unroll
                for (int mt = 0; mt < 2; mt++)
                    #pragma unroll
                    for (int nt = 0; nt < 4; nt++)
                        #pragma unroll
                        for (int q = 0; q < 4; q++) acc[mt][nt][q] = 0.0f;

                const uint4* hA = (const uint4*)g_h0H[(r + 1) & 1];   // h0[r-1]
                uint4 a[2][4][2];
                #pragma unroll
                for (int h2 = 0; h2 < 2; h2++)
                    #pragma unroll
                    for (int s = 0; s < 4; s++) {
                        int c = kq * 8 + h2 * 4 + s;
                        a[h2][s][0] = __ldcg(hA + (c * 2 + 0) * 32 + lane);
                        a[h2][s][1] = __ldcg(hA + (c * 2 + 1) * 32 + lane);
                    }
                #pragma unroll
                for (int h2 = 0; h2 < 2; h2++)
                    #pragma unroll
                    for (int s = 0; s < 4; s++) {
                        int si = h2 * 4 + s;
                        #pragma unroll
                        for (int nt = 0; nt < 4; nt++) {
                            uint2 w = *(const uint2*)(WshA + (((kq * 8 + si) * 4 + nt) << 6) + lane * 2);
                            mma_f16(acc[0][nt][0], acc[0][nt][1], acc[0][nt][2], acc[0][nt][3],
                                    a[h2][s][0].x, a[h2][s][0].y, a[h2][s][0].z, a[h2][s][0].w, w.x, w.y);
                            mma_f16(acc[1][nt][0], acc[1][nt][1], acc[1][nt][2], acc[1][nt][3],
                                    a[h2][s][1].x, a[h2][s][1].y, a[h2][s][1].z, a[h2][s][1].w, w.x, w.y);
                        }
                    }
                // packed partial store
                #pragma unroll
                for (int mt = 0; mt < 2; mt++)
                    #pragma unroll
                    for (int nt = 0; nt < 4; nt++) {
                        int row = kq * 32 + mt * 16 + g;
                        RshA[row * RPK + nt * 4 + t]       = pack_h2(acc[mt][nt][0], acc[mt][nt][1]);
                        RshA[(row + 8) * RPK + nt * 4 + t] = pack_h2(acc[mt][nt][2], acc[mt][nt][3]);
                    }
            }
            barn(1, 256);
            if (l0) {
                float s0 = xv0, s1 = xv1, s2 = xv2, s3 = xv3;
                const int sel = ej & 1;
                #pragma unroll
                for (int kk = 0; kk < 8; kk++) {
                    const unsigned* rp = RshA + (kk * 32 + eb) * RPK + (ej >> 1);
                    #pragma unroll
                    for (int q = 0; q < 4; q++) {
                        __half2 hv = *(const __half2*)&rp[q * 4];
                        float2 f = __half22float2(hv);
                        float v = sel ? f.y : f.x;
                        if (q == 0) s0 += v; else if (q == 1) s1 += v;
                        else if (q == 2) s2 += v; else s3 += v;
                    }
                }
                float iv = sigm(s0), fv = sigm(s1), gv = fast_tanh(s2), ov = sigm(s3);
                c0_state = fv * c0_state + iv * gv;
                float hval = ov * fast_tanh(c0_state);
                unsigned hb = (unsigned)__half_as_ushort(__float2half_rn(hval));
                unsigned ob = __shfl_xor_sync(0xffffffffu, hb, 1);
                if ((ej & 1) == 0)
                    g_h0H[r & 1][foff] = (hb & 0xffffu) | (ob << 16);
                hbuf[(r & 1) * 256 + cix] = __float2half_rn(hval);   // residual feed
            }
        } else {
            // ============ layer-1 chain (warps 8-15) ============
            const int kq = wid - 8;
            if (l1) {
                float acc[2][4][4];
                #pragma unroll
                for (int mt = 0; mt < 2; mt++)
                    #pragma unroll
                    for (int nt = 0; nt < 4; nt++)
                        #pragma unroll
                        for (int q = 0; q < 4; q++) acc[mt][nt][q] = 0.0f;

                const uint4* baseA;
                int cb;
                if (kq < 4) { baseA = (const uint4*)g_h0H[(r + 1) & 1]; cb = kq * 16; }   // h0[r-1]
                else        { baseA = (const uint4*)g_h1H[r & 1];       cb = (kq - 4) * 16; } // h1[r-2]

                uint4 b[2][2][2];
                #pragma unroll
                for (int s = 0; s < 2; s++) {
                    int c = cb + s;
                    b[0][s][0] = __ldcg(baseA + (c * 2 + 0) * 32 + lane);
                    b[0][s][1] = __ldcg(baseA + (c * 2 + 1) * 32 + lane);
                }
                #pragma unroll
                for (int wv = 0; wv < 8; wv++) {
                    int cur = wv & 1;
                    if (wv < 7) {
                        #pragma unroll
                        for (int s = 0; s < 2; s++) {
                            int c = cb + (wv + 1) * 2 + s;
                            b[1 - cur][s][0] = __ldcg(baseA + (c * 2 + 0) * 32 + lane);
                            b[1 - cur][s][1] = __ldcg(baseA + (c * 2 + 1) * 32 + lane);
                        }
                    }
                    #pragma unroll
                    for (int s = 0; s < 2; s++) {
                        int si = wv * 2 + s;
                        #pragma unroll
                        for (int nt = 0; nt < 4; nt++) {
                            uint2 w = *(const uint2*)(WshB + (((kq * 16 + si) * 4 + nt) << 6) + lane * 2);
                            mma_f16(acc[0][nt][0], acc[0][nt][1], acc[0][nt][2], acc[0][nt][3],
                                    b[cur][s][0].x, b[cur][s][0].y, b[cur][s][0].z, b[cur][s][0].w, w.x, w.y);
                            mma_f16(acc[1][nt][0], acc[1][nt][1], acc[1][nt][2], acc[1][nt][3],
                                    b[cur][s][1].x, b[cur][s][1].y, b[cur][s][1].z, b[cur][s][1].w, w.x, w.y);
                        }
                    }
                }
                #pragma unroll
                for (int mt = 0; mt < 2; mt++)
                    #pragma unroll
                    for (int nt = 0; nt < 4; nt++) {
                        int row = kq * 32 + mt * 16 + g;
                        RshB[row * RPK + nt * 4 + t]       = pack_h2(acc[mt][nt][0], acc[mt][nt][1]);
                        RshB[(row + 8) * RPK + nt * 4 + t] = pack_h2(acc[mt][nt][2], acc[mt][nt][3]);
                    }
            }
            barn(2, 256);
            if (l1) {
                float s0 = bias1[0], s1 = bias1[1], s2 = bias1[2], s3 = bias1[3];
                const int sel = ej & 1;
                #pragma unroll
                for (int kk = 0; kk < 8; kk++) {
                    const unsigned* rp = RshB + (kk * 32 + eb) * RPK + (ej >> 1);
                    #pragma unroll
                    for (int q = 0; q < 4; q++) {
                        __half2 hv = *(const __half2*)&rp[q * 4];
                        float2 f = __half22float2(hv);
                        float v = sel ? f.y : f.x;
                        if (q == 0) s0 += v; else if (q == 1) s1 += v;
                        else if (q == 2) s2 += v; else s3 += v;
                    }
                }
                float iv = sigm(s0), fv = sigm(s1), gv = fast_tanh(s2), ov = sigm(s3);
                c1_state = fv * c1_state + iv * gv;
                float h1val = ov * fast_tanh(c1_state);
                unsigned hb = (unsigned)__half_as_ushort(__float2half_rn(h1val));
                unsigned ob = __shfl_xor_sync(0xffffffffu, hb, 1);
                if ((ej & 1) == 0)
                    g_h1H[(r + 1) & 1][foff] = (hb & 0xffffu) | (ob << 16);
                float h0_res = __half2float(hbuf[((r + 1) & 1) * 256 + cix]);  // h0[r-1]
                outseq[((size_t)eb * T_ + (r - 1)) * H_ + hcol] = h1val + h0_res;
            }
        }

        grid_barrier((unsigned)(r + 2));
    }
}

// ---------------- launch ----------------
extern "C" void kernel_launch(void* const* d_in, const int* in_sizes, int n_in,
                              void* d_out, int out_size) {
    const float* x    = (const float*)d_in[0];
    const float* Wih0 = (const float*)d_in[1];
    const float* Whh0 = (const float*)d_in[2];
    const float* bih0 = (const float*)d_in[3];
    const float* bhh0 = (const float*)d_in[4];
    const float* Wih1 = (const float*)d_in[5];
    const float* Whh1 = (const float*)d_in[6];
    const float* bih1 = (const float*)d_in[7];
    const float* bhh1 = (const float*)d_in[8];
    float* out = (float*)d_out;

    cudaFuncSetAttribute(lstm_fused_kernel,
                         cudaFuncAttributeMaxDynamicSharedMemorySize, FUSED_SMEM);

    void* p;
    cudaGetSymbolAddress(&p, g_xg);     float* xg = (float*)p;
    cudaGetSymbolAddress(&p, g_arrive); unsigned* arr = (unsigned*)p;

    dim3 gg(32, 128);

    cudaMemsetAsync(arr, 0, sizeof(unsigned) * NCNT * CSTR);
    gemm_xg_kernel<<<gg, 256>>>(x, Wih0, bih0, bhh0, xg);
    lstm_fused_kernel<<<NBLK, NTHR, FUSED_SMEM>>>(xg, Whh0, Wih1, Whh1, bih1, bhh1, out);
}

// round 11
// speedup vs baseline: 2.2421x; 1.0069x over previous
#include <cuda_runtime.h>
#include <cuda_fp16.h>
#include <cstdint>

#define B_  32
#define T_  512
#define H_  1024
#define G4_ 4096
#define M_  (B_ * T_)   // 16384
#define NBLK 128
#define NTHR 512
#define NCNT 16
#define CSTR 64
#define BLKS_PER_CNT (NBLK / NCNT)

// ---------------- static device scratch ----------------
__device__ float g_xg[(size_t)M_ * G4_];     // layer-0 gate preactivations (from GEMM0)
__device__ unsigned g_h0H[2][16384];         // frag-permuted fp16 h0, parity-buffered
__device__ unsigned g_h1H[2][16384];
__device__ unsigned g_f0[NCNT * CSTR];       // h0-publish flags (striped)
__device__ unsigned g_f1[NCNT * CSTR];       // L1-done flags (striped)

// ---------------- helpers ----------------
__device__ __forceinline__ void mma_f16(float& c0, float& c1, float& c2, float& c3,
                                        uint32_t a0, uint32_t a1, uint32_t a2, uint32_t a3,
                                        uint32_t b0, uint32_t b1) {
    asm volatile(
        "mma.sync.aligned.m16n8k16.row.col.f32.f16.f16.f32 "
        "{%0,%1,%2,%3},{%4,%5,%6,%7},{%8,%9},{%0,%1,%2,%3};"
        : "+f"(c0), "+f"(c1), "+f"(c2), "+f"(c3)
        : "r"(a0), "r"(a1), "r"(a2), "r"(a3), "r"(b0), "r"(b1));
}

__device__ __forceinline__ float sigm(float x) {
    return __fdividef(1.0f, 1.0f + __expf(-x));
}

__device__ __forceinline__ float fast_tanh(float x) {
    x = fminf(fmaxf(x, -8.0f), 8.0f);
    float e = __expf(2.0f * x);
    return __fdividef(e - 1.0f, e + 1.0f);
}

__device__ __forceinline__ unsigned pack_h2(float a, float b) {
    __half2 h = __floats2half2_rn(a, b);
    return *(unsigned*)&h;
}

__device__ __forceinline__ void barn(int id, int cnt) {
    asm volatile("bar.sync %0, %1;" :: "r"(id), "r"(cnt) : "memory");
}

__device__ __forceinline__ void flag_release(unsigned* base) {
    asm volatile("red.release.gpu.global.add.u32 [%0], 1;"
                 :: "l"(&base[(blockIdx.x & (NCNT - 1)) * CSTR]) : "memory");
}

__device__ __forceinline__ void flag_poll(const unsigned* base, int idx, unsigned target) {
    const unsigned* cp = &base[idx * CSTR];
    unsigned v;
    do {
        asm volatile("ld.acquire.gpu.global.u32 %0, [%1];"
                     : "=r"(v) : "l"(cp) : "memory");
    } while (v < target);
}

// ---------------- big GEMM (fp16 mma): C[M,4096] = A[M,1024]*W^T + bias ----------------
#define GS_ 12

__global__ __launch_bounds__(256, 2)
void gemm_xg_kernel(const float* __restrict__ A,
                    const float* __restrict__ W,
                    const float* __restrict__ b0,
                    const float* __restrict__ b1,
                    float* __restrict__ C)
{
    __shared__ unsigned Ash[128 * GS_];
    __shared__ unsigned Bsh[128 * GS_];

    const int tid  = threadIdx.x;
    const int wid  = tid >> 5, lane = tid & 31;
    const int g    = lane >> 2, t = lane & 3;
    const int wm   = wid & 1, wn = wid >> 1;
    const int cm   = blockIdx.y * 128;
    const int cn   = blockIdx.x * 128;

    float acc[4][4][4];
    #pragma unroll
    for (int i = 0; i < 4; i++)
        #pragma unroll
        for (int j = 0; j < 4; j++)
            #pragma unroll
            for (int q = 0; q < 4; q++) acc[i][j][q] = 0.0f;

    const int r0 = tid >> 1;
    const int q0 = tid & 1;

    const float* Ag = A + (size_t)(cm + r0) * 1024 + 8 * q0;
    const float* Bg = W + (size_t)(cn + r0) * 1024 + 8 * q0;

    float4 av0 = *(const float4*)(Ag);
    float4 av1 = *(const float4*)(Ag + 4);
    float4 bv0 = *(const float4*)(Bg);
    float4 bv1 = *(const float4*)(Bg + 4);

    for (int kk = 0; kk < 1024; kk += 16) {
        __syncthreads();
        {
            uint4 pa, pb;
            pa.x = pack_h2(av0.x, av0.y); pa.y = pack_h2(av0.z, av0.w);
            pa.z = pack_h2(av1.x, av1.y); pa.w = pack_h2(av1.z, av1.w);
            pb.x = pack_h2(bv0.x, bv0.y); pb.y = pack_h2(bv0.z, bv0.w);
            pb.z = pack_h2(bv1.x, bv1.y); pb.w = pack_h2(bv1.z, bv1.w);
            *(uint4*)(Ash + r0 * GS_ + 4 * q0) = pa;
            *(uint4*)(Bsh + r0 * GS_ + 4 * q0) = pb;
        }
        __syncthreads();

        if (kk + 16 < 1024) {
            av0 = *(const float4*)(Ag + kk + 16);
            av1 = *(const float4*)(Ag + kk + 20);
            bv0 = *(const float4*)(Bg + kk + 16);
            bv1 = *(const float4*)(Bg + kk + 20);
        }

        uint32_t af[4][4];
        uint32_t bf[4][2];
        #pragma unroll
        for (int mt = 0; mt < 4; mt++) {
            int rb = wm * 64 + mt * 16;
            af[mt][0] = Ash[(rb + g)     * GS_ + t];
            af[mt][1] = Ash[(rb + g + 8) * GS_ + t];
            af[mt][2] = Ash[(rb + g)     * GS_ + t + 4];
            af[mt][3] = Ash[(rb + g + 8) * GS_ + t + 4];
        }
        #pragma unroll
        for (int nt = 0; nt < 4; nt++) {
            int nb = wn * 32 + nt * 8 + g;
            bf[nt][0] = Bsh[nb * GS_ + t];
            bf[nt][1] = Bsh[nb * GS_ + t + 4];
        }
        #pragma unroll
        for (int mt = 0; mt < 4; mt++)
            #pragma unroll
            for (int nt = 0; nt < 4; nt++)
                mma_f16(acc[mt][nt][0], acc[mt][nt][1], acc[mt][nt][2], acc[mt][nt][3],
                        af[mt][0], af[mt][1], af[mt][2], af[mt][3],
                        bf[nt][0], bf[nt][1]);
    }

    #pragma unroll
    for (int mt = 0; mt < 4; mt++) {
        #pragma unroll
        for (int nt = 0; nt < 4; nt++) {
            int m = cm + wm * 64 + mt * 16 + g;
            int n = cn + wn * 32 + nt * 8 + 2 * t;
            float bs0 = b0[n] + b1[n];
            float bs1 = b0[n + 1] + b1[n + 1];
            float2 v0 = make_float2(acc[mt][nt][0] + bs0, acc[mt][nt][1] + bs1);
            float2 v1 = make_float2(acc[mt][nt][2] + bs0, acc[mt][nt][3] + bs1);
            *(float2*)(C + (size_t)m * G4_ + n) = v0;
            *(float2*)(C + (size_t)(m + 8) * G4_ + n) = v1;
        }
    }
}

// ---------------- fused two-layer scan, decoupled dataflow chains ----------------
// Warps 8-15 = layer-0 (critical path, high arbiter priority); warps 0-7 = layer-1.
// f0 flags: h0[r] published (phase r+2). f1 flags: L1 round r fully done (phase r).
// Both halves wait (f0 >= r+1, f1 >= r-1): bounds L1 lag to 1 round -> all
// parity double-buffers (h0, h1, hbuf) are overwrite-safe by flag transitivity.
#define WA_  16384
#define WB_  32768
#define RPK  17
#define RPKS (8 * 32 * RPK)
#define FUSED_SMEM ((WA_ + WB_ + 2 * RPKS + 256) * 4)   // 232448 B

__global__ __launch_bounds__(NTHR, 1)
void lstm_fused_kernel(const float* __restrict__ xg,
                       const float* __restrict__ Whh0,
                       const float* __restrict__ Wih1,
                       const float* __restrict__ Whh1,
                       const float* __restrict__ bih1,
                       const float* __restrict__ bhh1,
                       float* __restrict__ outseq)
{
    extern __shared__ unsigned smu[];
    unsigned* WshA = smu;
    unsigned* WshB = smu + WA_;
    unsigned* RshA = smu + WA_ + WB_;
    unsigned* RshB = RshA + RPKS;
    __half*   hbuf = (__half*)(RshB + RPKS);    // [2][256]

    const int tid  = threadIdx.x;
    const int bid  = blockIdx.x;
    const int wid  = tid >> 5, lane = tid & 31;
    const int g    = lane >> 2, t = lane & 3;

    // ---- fill Whh0 frags ----
    for (int e = tid; e < WA_; e += NTHR) {
        int rr = e & 1;
        int ln = (e >> 1) & 31;
        int nt = (e >> 6) & 3;
        int si = (e >> 8) & 7;
        int kq = e >> 11;
        int n8 = ln >> 2, tt = ln & 3;
        int row = nt * 1024 + bid * 8 + n8;
        int k0  = kq * 128 + si * 16 + 2 * tt + rr * 8;
        WshA[e] = pack_h2(Whh0[(size_t)row * 1024 + k0],
                          Whh0[(size_t)row * 1024 + k0 + 1]);
    }
    // ---- fill [Wih1|Whh1] frags (K=2048) ----
    for (int e = tid; e < WB_; e += NTHR) {
        int rr = e & 1;
        int ln = (e >> 1) & 31;
        int nt = (e >> 6) & 3;
        int si = (e >> 8) & 15;
        int kq = e >> 12;
        int n8 = ln >> 2, tt = ln & 3;
        int row = nt * 1024 + bid * 8 + n8;
        int kg  = kq * 256 + si * 16 + 2 * tt + rr * 8;
        const float* src = (kg < 1024) ? (Wih1 + (size_t)row * 1024 + kg)
                                       : (Whh1 + (size_t)row * 1024 + (kg - 1024));
        WshB[e] = pack_h2(src[0], src[1]);
    }

    const int cix  = tid & 255;
    const int eb   = cix >> 3;
    const int ej   = cix & 7;
    const int hcol = bid * 8 + ej;
    const int c_   = bid >> 1;
    const int fmt  = eb >> 4;
    const int ridx = (bid & 1) * 2 + ((eb >> 3) & 1);
    const int foff = (((c_ * 2 + fmt) * 32) + (eb & 7) * 4 + (ej >> 1)) * 4 + ridx;

    float c0_state = 0.0f, c1_state = 0.0f;
    float bias1[4];
    if (tid >= 256) {                           // L0 half
        if ((ej & 1) == 0) g_h0H[1][foff] = 0u; // h0[-1] = 0 (parity 1)
    } else {                                    // L1 half
        #pragma unroll
        for (int q = 0; q < 4; q++)
            bias1[q] = bih1[q * 1024 + hcol] + bhh1[q * 1024 + hcol];
        if ((ej & 1) == 0) g_h1H[1][foff] = 0u; // h1[-1] = 0 (parity 1)
    }

    // init publish (f0 phase 1), after zero-buffers are written
    __syncthreads();
    if (tid == 0) flag_release(g_f0);

    if (tid >= 256) {
        // ================= layer-0 chain (warps 8-15) =================
        const int kq = wid - 8;
        const int local = tid - 256;
        for (int r = 0; r < T_; r++) {
            // prefetch xg (independent of flags)
            const float* xp = xg + ((size_t)eb * T_ + r) * G4_ + hcol;
            float xv0 = __ldcs(xp);
            float xv1 = __ldcs(xp + 1024);
            float xv2 = __ldcs(xp + 2048);
            float xv3 = __ldcs(xp + 3072);

            // wait: h0[r-1] published; L1 round r-1 fully done (bounds lag)
            if (local < 16) flag_poll(g_f0, local, (unsigned)(r + 1) * BLKS_PER_CNT);
            else if (local < 32 && r >= 1)
                flag_poll(g_f1, local - 16, (unsigned)(r - 1) * BLKS_PER_CNT);
            barn(3, 256);

            float acc[2][4][4];
            #pragma unroll
            for (int mt = 0; mt < 2; mt++)
                #pragma unroll
                for (int nt = 0; nt < 4; nt++)
                    #pragma unroll
                    for (int q = 0; q < 4; q++) acc[mt][nt][q] = 0.0f;

            const uint4* hA = (const uint4*)g_h0H[(r + 1) & 1];   // h0[r-1]
            uint4 a[2][4][2];
            #pragma unroll
            for (int h2 = 0; h2 < 2; h2++)
                #pragma unroll
                for (int s = 0; s < 4; s++) {
                    int c = kq * 8 + h2 * 4 + s;
                    a[h2][s][0] = __ldcg(hA + (c * 2 + 0) * 32 + lane);
                    a[h2][s][1] = __ldcg(hA + (c * 2 + 1) * 32 + lane);
                }
            #pragma unroll
            for (int h2 = 0; h2 < 2; h2++)
                #pragma unroll
                for (int s = 0; s < 4; s++) {
                    int si = h2 * 4 + s;
                    #pragma unroll
                    for (int nt = 0; nt < 4; nt++) {
                        uint2 w = *(const uint2*)(WshA + (((kq * 8 + si) * 4 + nt) << 6) + lane * 2);
                        mma_f16(acc[0][nt][0], acc[0][nt][1], acc[0][nt][2], acc[0][nt][3],
                                a[h2][s][0].x, a[h2][s][0].y, a[h2][s][0].z, a[h2][s][0].w, w.x, w.y);
                        mma_f16(acc[1][nt][0], acc[1][nt][1], acc[1][nt][2], acc[1][nt][3],
                                a[h2][s][1].x, a[h2][s][1].y, a[h2][s][1].z, a[h2][s][1].w, w.x, w.y);
                    }
                }
            #pragma unroll
            for (int mt = 0; mt < 2; mt++)
                #pragma unroll
                for (int nt = 0; nt < 4; nt++) {
                    int row = kq * 32 + mt * 16 + g;
                    RshA[row * RPK + nt * 4 + t]       = pack_h2(acc[mt][nt][0], acc[mt][nt][1]);
                    RshA[(row + 8) * RPK + nt * 4 + t] = pack_h2(acc[mt][nt][2], acc[mt][nt][3]);
                }
            barn(1, 256);

            {
                float s0 = xv0, s1 = xv1, s2 = xv2, s3 = xv3;
                const int sel = ej & 1;
                #pragma unroll
                for (int kk = 0; kk < 8; kk++) {
                    const unsigned* rp = RshA + (kk * 32 + eb) * RPK + (ej >> 1);
                    #pragma unroll
                    for (int q = 0; q < 4; q++) {
                        __half2 hv = *(const __half2*)&rp[q * 4];
                        float2 f = __half22float2(hv);
                        float v = sel ? f.y : f.x;
                        if (q == 0) s0 += v; else if (q == 1) s1 += v;
                        else if (q == 2) s2 += v; else s3 += v;
                    }
                }
                float iv = sigm(s0), fv = sigm(s1), gv = fast_tanh(s2), ov = sigm(s3);
                c0_state = fv * c0_state + iv * gv;
                float hval = ov * fast_tanh(c0_state);
                unsigned hb = (unsigned)__half_as_ushort(__float2half_rn(hval));
                unsigned ob = __shfl_xor_sync(0xffffffffu, hb, 1);
                if ((ej & 1) == 0)
                    g_h0H[r & 1][foff] = (hb & 0xffffu) | (ob << 16);
                hbuf[(r & 1) * 256 + cix] = __float2half_rn(hval);
            }
            barn(2, 256);
            if (local == 0) flag_release(g_f0);   // f0 phase r+2
        }
    } else {
        // ================= layer-1 chain (warps 0-7) =================
        const int kq = wid;
        for (int r = 1; r <= T_; r++) {
            if (tid < 16) flag_poll(g_f0, tid, (unsigned)(r + 1) * BLKS_PER_CNT);
            else if (tid < 32 && r >= 2)
                flag_poll(g_f1, tid - 16, (unsigned)(r - 1) * BLKS_PER_CNT);
            barn(6, 256);

            float acc[2][4][4];
            #pragma unroll
            for (int mt = 0; mt < 2; mt++)
                #pragma unroll
                for (int nt = 0; nt < 4; nt++)
                    #pragma unroll
                    for (int q = 0; q < 4; q++) acc[mt][nt][q] = 0.0f;

            const uint4* baseA;
            int cb;
            if (kq < 4) { baseA = (const uint4*)g_h0H[(r + 1) & 1]; cb = kq * 16; }       // h0[r-1]
            else        { baseA = (const uint4*)g_h1H[r & 1];       cb = (kq - 4) * 16; } // h1[r-2]

            uint4 b[2][2][2];
            #pragma unroll
            for (int s = 0; s < 2; s++) {
                int c = cb + s;
                b[0][s][0] = __ldcg(baseA + (c * 2 + 0) * 32 + lane);
                b[0][s][1] = __ldcg(baseA + (c * 2 + 1) * 32 + lane);
            }
            #pragma unroll
            for (int wv = 0; wv < 8; wv++) {
                int cur = wv & 1;
                if (wv < 7) {
                    #pragma unroll
                    for (int s = 0; s < 2; s++) {
                        int c = cb + (wv + 1) * 2 + s;
                        b[1 - cur][s][0] = __ldcg(baseA + (c * 2 + 0) * 32 + lane);
                        b[1 - cur][s][1] = __ldcg(baseA + (c * 2 + 1) * 32 + lane);
                    }
                }
                #pragma unroll
                for (int s = 0; s < 2; s++) {
                    int si = wv * 2 + s;
                    #pragma unroll
                    for (int nt = 0; nt < 4; nt++) {
                        uint2 w = *(const uint2*)(WshB + (((kq * 16 + si) * 4 + nt) << 6) + lane * 2);
                        mma_f16(acc[0][nt][0], acc[0][nt][1], acc[0][nt][2], acc[0][nt][3],
                                b[cur][s][0].x, b[cur][s][0].y, b[cur][s][0].z, b[cur][s][0].w, w.x, w.y);
                        mma_f16(acc[1][nt][0], acc[1][nt][1], acc[1][nt][2], acc[1][nt][3],
                                b[cur][s][1].x, b[cur][s][1].y, b[cur][s][1].z, b[cur][s][1].w, w.x, w.y);
                    }
                }
            }
            #pragma unroll
            for (int mt = 0; mt < 2; mt++)
                #pragma unroll
                for (int nt = 0; nt < 4; nt++) {
                    int row = kq * 32 + mt * 16 + g;
                    RshB[row * RPK + nt * 4 + t]       = pack_h2(acc[mt][nt][0], acc[mt][nt][1]);
                    RshB[(row + 8) * RPK + nt * 4 + t] = pack_h2(acc[mt][nt][2], acc[mt][nt][3]);
                }
            barn(4, 256);

            {
                float s0 = bias1[0], s1 = bias1[1], s2 = bias1[2], s3 = bias1[3];
                const int sel = ej & 1;
                #pragma unroll
                for (int kk = 0; kk < 8; kk++) {
                    const unsigned* rp = RshB + (kk * 32 + eb) * RPK + (ej >> 1);
                    #pragma unroll
                    for (int q = 0; q < 4; q++) {
                        __half2 hv = *(const __half2*)&rp[q * 4];
                        float2 f = __half22float2(hv);
                        float v = sel ? f.y : f.x;
                        if (q == 0) s0 += v; else if (q == 1) s1 += v;
                        else if (q == 2) s2 += v; else s3 += v;
                    }
                }
                float iv = sigm(s0), fv = sigm(s1), gv = fast_tanh(s2), ov = sigm(s3);
                c1_state = fv * c1_state + iv * gv;
                float h1val = ov * fast_tanh(c1_state);
                unsigned hb = (unsigned)__half_as_ushort(__float2half_rn(h1val));
                unsigned ob = __shfl_xor_sync(0xffffffffu, hb, 1);
                if ((ej & 1) == 0)
                    g_h1H[(r + 1) & 1][foff] = (hb & 0xffffu) | (ob << 16);
                float h0_res = __half2float(hbuf[((r + 1) & 1) * 256 + cix]);  // h0[r-1]
                outseq[((size_t)eb * T_ + (r - 1)) * H_ + hcol] = h1val + h0_res;
            }
            barn(5, 256);
            if (tid == 0) flag_release(g_f1);     // f1 phase r
        }
    }
}

// ---------------- launch ----------------
extern "C" void kernel_launch(void* const* d_in, const int* in_sizes, int n_in,
                              void* d_out, int out_size) {
    const float* x    = (const float*)d_in[0];
    const float* Wih0 = (const float*)d_in[1];
    const float* Whh0 = (const float*)d_in[2];
    const float* bih0 = (const float*)d_in[3];
    const float* bhh0 = (const float*)d_in[4];
    const float* Wih1 = (const float*)d_in[5];
    const float* Whh1 = (const float*)d_in[6];
    const float* bih1 = (const float*)d_in[7];
    const float* bhh1 = (const float*)d_in[8];
    float* out = (float*)d_out;

    cudaFuncSetAttribute(lstm_fused_kernel,
                         cudaFuncAttributeMaxDynamicSharedMemorySize, FUSED_SMEM);

    void* p;
    cudaGetSymbolAddress(&p, g_xg);  float* xg = (float*)p;
    cudaGetSymbolAddress(&p, g_f0);  unsigned* f0 = (unsigned*)p;
    cudaGetSymbolAddress(&p, g_f1);  unsigned* f1 = (unsigned*)p;

    dim3 gg(32, 128);

    cudaMemsetAsync(f0, 0, sizeof(unsigned) * NCNT * CSTR);
    cudaMemsetAsync(f1, 0, sizeof(unsigned) * NCNT * CSTR);
    gemm_xg_kernel<<<gg, 256>>>(x, Wih0, bih0, bhh0, xg);
    lstm_fused_kernel<<<NBLK, NTHR, FUSED_SMEM>>>(xg, Whh0, Wih1, Whh1, bih1, bhh1, out);
}

// round 12
// speedup vs baseline: 2.2438x; 1.0008x over previous
#include <cuda_runtime.h>
#include <cuda_fp16.h>
#include <cstdint>

#define B_  32
#define T_  512
#define H_  1024
#define G4_ 4096
#define M_  (B_ * T_)   // 16384
#define NBLK 128
#define NTHR 512
#define NCNT 16
#define CSTR 64
#define BLKS_PER_CNT (NBLK / NCNT)

// ---------------- static device scratch ----------------
__device__ float g_xg[(size_t)M_ * G4_];     // layer-0 gate preactivations (from GEMM0)
__device__ unsigned g_h0H[2][16384];         // frag-permuted fp16 h0, parity-buffered
__device__ unsigned g_h1H[2][16384];
__device__ unsigned g_f0[NCNT * CSTR];       // h0-publish flags (striped)
__device__ unsigned g_f1[NCNT * CSTR];       // L1-done flags (striped)

// ---------------- helpers ----------------
__device__ __forceinline__ void mma_f16(float& c0, float& c1, float& c2, float& c3,
                                        uint32_t a0, uint32_t a1, uint32_t a2, uint32_t a3,
                                        uint32_t b0, uint32_t b1) {
    asm volatile(
        "mma.sync.aligned.m16n8k16.row.col.f32.f16.f16.f32 "
        "{%0,%1,%2,%3},{%4,%5,%6,%7},{%8,%9},{%0,%1,%2,%3};"
        : "+f"(c0), "+f"(c1), "+f"(c2), "+f"(c3)
        : "r"(a0), "r"(a1), "r"(a2), "r"(a3), "r"(b0), "r"(b1));
}

__device__ __forceinline__ float sigm(float x) {
    return __fdividef(1.0f, 1.0f + __expf(-x));
}

__device__ __forceinline__ float fast_tanh(float x) {
    x = fminf(fmaxf(x, -8.0f), 8.0f);
    float e = __expf(2.0f * x);
    return __fdividef(e - 1.0f, e + 1.0f);
}

__device__ __forceinline__ unsigned pack_h2(float a, float b) {
    __half2 h = __floats2half2_rn(a, b);
    return *(unsigned*)&h;
}

__device__ __forceinline__ void barn(int id, int cnt) {
    asm volatile("bar.sync %0, %1;" :: "r"(id), "r"(cnt) : "memory");
}

__device__ __forceinline__ void flag_release(unsigned* base) {
    asm volatile("red.release.gpu.global.add.u32 [%0], 1;"
                 :: "l"(&base[(blockIdx.x & (NCNT - 1)) * CSTR]) : "memory");
}

__device__ __forceinline__ void flag_poll(const unsigned* base, int idx, unsigned target) {
    const unsigned* cp = &base[idx * CSTR];
    unsigned v;
    do {
        asm volatile("ld.acquire.gpu.global.u32 %0, [%1];"
                     : "=r"(v) : "l"(cp) : "memory");
    } while (v < target);
}

// ---------------- big GEMM (fp16 mma): C[M,4096] = A[M,1024]*W^T + bias ----------------
#define GS_ 12

__global__ __launch_bounds__(256, 2)
void gemm_xg_kernel(const float* __restrict__ A,
                    const float* __restrict__ W,
                    const float* __restrict__ b0,
                    const float* __restrict__ b1,
                    float* __restrict__ C)
{
    __shared__ unsigned Ash[128 * GS_];
    __shared__ unsigned Bsh[128 * GS_];

    const int tid  = threadIdx.x;
    const int wid  = tid >> 5, lane = tid & 31;
    const int g    = lane >> 2, t = lane & 3;
    const int wm   = wid & 1, wn = wid >> 1;
    const int cm   = blockIdx.y * 128;
    const int cn   = blockIdx.x * 128;

    float acc[4][4][4];
    #pragma unroll
    for (int i = 0; i < 4; i++)
        #pragma unroll
        for (int j = 0; j < 4; j++)
            #pragma unroll
            for (int q = 0; q < 4; q++) acc[i][j][q] = 0.0f;

    const int r0 = tid >> 1;
    const int q0 = tid & 1;

    const float* Ag = A + (size_t)(cm + r0) * 1024 + 8 * q0;
    const float* Bg = W + (size_t)(cn + r0) * 1024 + 8 * q0;

    float4 av0 = *(const float4*)(Ag);
    float4 av1 = *(const float4*)(Ag + 4);
    float4 bv0 = *(const float4*)(Bg);
    float4 bv1 = *(const float4*)(Bg + 4);

    for (int kk = 0; kk < 1024; kk += 16) {
        __syncthreads();
        {
            uint4 pa, pb;
            pa.x = pack_h2(av0.x, av0.y); pa.y = pack_h2(av0.z, av0.w);
            pa.z = pack_h2(av1.x, av1.y); pa.w = pack_h2(av1.z, av1.w);
            pb.x = pack_h2(bv0.x, bv0.y); pb.y = pack_h2(bv0.z, bv0.w);
            pb.z = pack_h2(bv1.x, bv1.y); pb.w = pack_h2(bv1.z, bv1.w);
            *(uint4*)(Ash + r0 * GS_ + 4 * q0) = pa;
            *(uint4*)(Bsh + r0 * GS_ + 4 * q0) = pb;
        }
        __syncthreads();

        if (kk + 16 < 1024) {
            av0 = *(const float4*)(Ag + kk + 16);
            av1 = *(const float4*)(Ag + kk + 20);
            bv0 = *(const float4*)(Bg + kk + 16);
            bv1 = *(const float4*)(Bg + kk + 20);
        }

        uint32_t af[4][4];
        uint32_t bf[4][2];
        #pragma unroll
        for (int mt = 0; mt < 4; mt++) {
            int rb = wm * 64 + mt * 16;
            af[mt][0] = Ash[(rb + g)     * GS_ + t];
            af[mt][1] = Ash[(rb + g + 8) * GS_ + t];
            af[mt][2] = Ash[(rb + g)     * GS_ + t + 4];
            af[mt][3] = Ash[(rb + g + 8) * GS_ + t + 4];
        }
        #pragma unroll
        for (int nt = 0; nt < 4; nt++) {
            int nb = wn * 32 + nt * 8 + g;
            bf[nt][0] = Bsh[nb * GS_ + t];
            bf[nt][1] = Bsh[nb * GS_ + t + 4];
        }
        #pragma unroll
        for (int mt = 0; mt < 4; mt++)
            #pragma unroll
            for (int nt = 0; nt < 4; nt++)
                mma_f16(acc[mt][nt][0], acc[mt][nt][1], acc[mt][nt][2], acc[mt][nt][3],
                        af[mt][0], af[mt][1], af[mt][2], af[mt][3],
                        bf[nt][0], bf[nt][1]);
    }

    #pragma unroll
    for (int mt = 0; mt < 4; mt++) {
        #pragma unroll
        for (int nt = 0; nt < 4; nt++) {
            int m = cm + wm * 64 + mt * 16 + g;
            int n = cn + wn * 32 + nt * 8 + 2 * t;
            float bs0 = b0[n] + b1[n];
            float bs1 = b0[n + 1] + b1[n + 1];
            float2 v0 = make_float2(acc[mt][nt][0] + bs0, acc[mt][nt][1] + bs1);
            float2 v1 = make_float2(acc[mt][nt][2] + bs0, acc[mt][nt][3] + bs1);
            *(float2*)(C + (size_t)m * G4_ + n) = v0;
            *(float2*)(C + (size_t)(m + 8) * G4_ + n) = v1;
        }
    }
}

// ---------------- fused two-layer scan, decoupled dataflow chains ----------------
// Warps 8-15 = layer-0 (critical path, high arbiter priority); warps 0-7 = layer-1.
// f0 flags: h0[r] published (phase r+2). f1 flags: L1 round r fully done (phase r).
// Both halves wait (f0 >= r+1, f1 >= r-1): bounds L1 lag to 1 round -> all
// parity double-buffers (h0, h1, hbuf) are overwrite-safe by flag transitivity.
#define WA_  16384
#define WB_  32768
#define RPK  17
#define RPKS (8 * 32 * RPK)
#define FUSED_SMEM ((WA_ + WB_ + 2 * RPKS + 256) * 4)   // 232448 B

__global__ __launch_bounds__(NTHR, 1)
void lstm_fused_kernel(const float* __restrict__ xg,
                       const float* __restrict__ Whh0,
                       const float* __restrict__ Wih1,
                       const float* __restrict__ Whh1,
                       const float* __restrict__ bih1,
                       const float* __restrict__ bhh1,
                       float* __restrict__ outseq)
{
    extern __shared__ unsigned smu[];
    unsigned* WshA = smu;
    unsigned* WshB = smu + WA_;
    unsigned* RshA = smu + WA_ + WB_;
    unsigned* RshB = RshA + RPKS;
    __half*   hbuf = (__half*)(RshB + RPKS);    // [2][256]

    const int tid  = threadIdx.x;
    const int bid  = blockIdx.x;
    const int wid  = tid >> 5, lane = tid & 31;
    const int g    = lane >> 2, t = lane & 3;

    // ---- fill Whh0 frags ----
    for (int e = tid; e < WA_; e += NTHR) {
        int rr = e & 1;
        int ln = (e >> 1) & 31;
        int nt = (e >> 6) & 3;
        int si = (e >> 8) & 7;
        int kq = e >> 11;
        int n8 = ln >> 2, tt = ln & 3;
        int row = nt * 1024 + bid * 8 + n8;
        int k0  = kq * 128 + si * 16 + 2 * tt + rr * 8;
        WshA[e] = pack_h2(Whh0[(size_t)row * 1024 + k0],
                          Whh0[(size_t)row * 1024 + k0 + 1]);
    }
    // ---- fill [Wih1|Whh1] frags (K=2048) ----
    for (int e = tid; e < WB_; e += NTHR) {
        int rr = e & 1;
        int ln = (e >> 1) & 31;
        int nt = (e >> 6) & 3;
        int si = (e >> 8) & 15;
        int kq = e >> 12;
        int n8 = ln >> 2, tt = ln & 3;
        int row = nt * 1024 + bid * 8 + n8;
        int kg  = kq * 256 + si * 16 + 2 * tt + rr * 8;
        const float* src = (kg < 1024) ? (Wih1 + (size_t)row * 1024 + kg)
                                       : (Whh1 + (size_t)row * 1024 + (kg - 1024));
        WshB[e] = pack_h2(src[0], src[1]);
    }

    const int cix  = tid & 255;
    const int eb   = cix >> 3;
    const int ej   = cix & 7;
    const int hcol = bid * 8 + ej;
    const int c_   = bid >> 1;
    const int fmt  = eb >> 4;
    const int ridx = (bid & 1) * 2 + ((eb >> 3) & 1);
    const int foff = (((c_ * 2 + fmt) * 32) + (eb & 7) * 4 + (ej >> 1)) * 4 + ridx;

    float c0_state = 0.0f, c1_state = 0.0f;
    float bias1[4];
    if (tid >= 256) {                           // L0 half
        if ((ej & 1) == 0) g_h0H[1][foff] = 0u; // h0[-1] = 0 (parity 1)
    } else {                                    // L1 half
        #pragma unroll
        for (int q = 0; q < 4; q++)
            bias1[q] = bih1[q * 1024 + hcol] + bhh1[q * 1024 + hcol];
        if ((ej & 1) == 0) g_h1H[1][foff] = 0u; // h1[-1] = 0 (parity 1)
    }

    // init publish (f0 phase 1), after zero-buffers are written
    __syncthreads();
    if (tid == 0) flag_release(g_f0);

    if (tid >= 256) {
        // ================= layer-0 chain (warps 8-15) =================
        const int kq = wid - 8;
        const int local = tid - 256;
        for (int r = 0; r < T_; r++) {
            // prefetch xg (independent of flags)
            const float* xp = xg + ((size_t)eb * T_ + r) * G4_ + hcol;
            float xv0 = __ldcs(xp);
            float xv1 = __ldcs(xp + 1024);
            float xv2 = __ldcs(xp + 2048);
            float xv3 = __ldcs(xp + 3072);

            // wait: h0[r-1] published; L1 round r-1 fully done (bounds lag)
            if (local < 16) flag_poll(g_f0, local, (unsigned)(r + 1) * BLKS_PER_CNT);
            else if (local < 32 && r >= 1)
                flag_poll(g_f1, local - 16, (unsigned)(r - 1) * BLKS_PER_CNT);
            barn(3, 256);

            float acc[2][4][4];
            #pragma unroll
            for (int mt = 0; mt < 2; mt++)
                #pragma unroll
                for (int nt = 0; nt < 4; nt++)
                    #pragma unroll
                    for (int q = 0; q < 4; q++) acc[mt][nt][q] = 0.0f;

            const uint4* hA = (const uint4*)g_h0H[(r + 1) & 1];   // h0[r-1]
            uint4 a[2][4][2];
            #pragma unroll
            for (int h2 = 0; h2 < 2; h2++)
                #pragma unroll
                for (int s = 0; s < 4; s++) {
                    int c = kq * 8 + h2 * 4 + s;
                    a[h2][s][0] = __ldcg(hA + (c * 2 + 0) * 32 + lane);
                    a[h2][s][1] = __ldcg(hA + (c * 2 + 1) * 32 + lane);
                }
            #pragma unroll
            for (int h2 = 0; h2 < 2; h2++)
                #pragma unroll
                for (int s = 0; s < 4; s++) {
                    int si = h2 * 4 + s;
                    #pragma unroll
                    for (int nt = 0; nt < 4; nt++) {
                        uint2 w = *(const uint2*)(WshA + (((kq * 8 + si) * 4 + nt) << 6) + lane * 2);
                        mma_f16(acc[0][nt][0], acc[0][nt][1], acc[0][nt][2], acc[0][nt][3],
                                a[h2][s][0].x, a[h2][s][0].y, a[h2][s][0].z, a[h2][s][0].w, w.x, w.y);
                        mma_f16(acc[1][nt][0], acc[1][nt][1], acc[1][nt][2], acc[1][nt][3],
                                a[h2][s][1].x, a[h2][s][1].y, a[h2][s][1].z, a[h2][s][1].w, w.x, w.y);
                    }
                }
            #pragma unroll
            for (int mt = 0; mt < 2; mt++)
                #pragma unroll
                for (int nt = 0; nt < 4; nt++) {
                    int row = kq * 32 + mt * 16 + g;
                    RshA[row * RPK + nt * 4 + t]       = pack_h2(acc[mt][nt][0], acc[mt][nt][1]);
                    RshA[(row + 8) * RPK + nt * 4 + t] = pack_h2(acc[mt][nt][2], acc[mt][nt][3]);
                }
            barn(1, 256);

            {
                float s0 = xv0, s1 = xv1, s2 = xv2, s3 = xv3;
                const int sel = ej & 1;
                #pragma unroll
                for (int kk = 0; kk < 8; kk++) {
                    const unsigned* rp = RshA + (kk * 32 + eb) * RPK + (ej >> 1);
                    #pragma unroll
                    for (int q = 0; q < 4; q++) {
                        __half2 hv = *(const __half2*)&rp[q * 4];
                        float2 f = __half22float2(hv);
                        float v = sel ? f.y : f.x;
                        if (q == 0) s0 += v; else if (q == 1) s1 += v;
                        else if (q == 2) s2 += v; else s3 += v;
                    }
                }
                float iv = sigm(s0), fv = sigm(s1), gv = fast_tanh(s2), ov = sigm(s3);
                c0_state = fv * c0_state + iv * gv;
                float hval = ov * fast_tanh(c0_state);
                unsigned hb = (unsigned)__half_as_ushort(__float2half_rn(hval));
                unsigned ob = __shfl_xor_sync(0xffffffffu, hb, 1);
                if ((ej & 1) == 0)
                    g_h0H[r & 1][foff] = (hb & 0xffffu) | (ob << 16);
                hbuf[(r & 1) * 256 + cix] = __float2half_rn(hval);
            }
            barn(2, 256);
            if (local == 0) flag_release(g_f0);   // f0 phase r+2
        }
    } else {
        // ================= layer-1 chain (warps 0-7) =================
        const int kq = wid;
        for (int r = 1; r <= T_; r++) {
            if (tid < 16) flag_poll(g_f0, tid, (unsigned)(r + 1) * BLKS_PER_CNT);
            else if (tid < 32 && r >= 2)
                flag_poll(g_f1, tid - 16, (unsigned)(r - 1) * BLKS_PER_CNT);
            barn(6, 256);

            float acc[2][4][4];
            #pragma unroll
            for (int mt = 0; mt < 2; mt++)
                #pragma unroll
                for (int nt = 0; nt < 4; nt++)
                    #pragma unroll
                    for (int q = 0; q < 4; q++) acc[mt][nt][q] = 0.0f;

            const uint4* baseA;
            int cb;
            if (kq < 4) { baseA = (const uint4*)g_h0H[(r + 1) & 1]; cb = kq * 16; }       // h0[r-1]
            else        { baseA = (const uint4*)g_h1H[r & 1];       cb = (kq - 4) * 16; } // h1[r-2]

            uint4 b[2][2][2];
            #pragma unroll
            for (int s = 0; s < 2; s++) {
                int c = cb + s;
                b[0][s][0] = __ldcg(baseA + (c * 2 + 0) * 32 + lane);
                b[0][s][1] = __ldcg(baseA + (c * 2 + 1) * 32 + lane);
            }
            #pragma unroll
            for (int wv = 0; wv < 8; wv++) {
                int cur = wv & 1;
                if (wv < 7) {
                    #pragma unroll
                    for (int s = 0; s < 2; s++) {
                        int c = cb + (wv + 1) * 2 + s;
                        b[1 - cur][s][0] = __ldcg(baseA + (c * 2 + 0) * 32 + lane);
                        b[1 - cur][s][1] = __ldcg(baseA + (c * 2 + 1) * 32 + lane);
                    }
                }
                #pragma unroll
                for (int s = 0; s < 2; s++) {
                    int si = wv * 2 + s;
                    #pragma unroll
                    for (int nt = 0; nt < 4; nt++) {
                        uint2 w = *(const uint2*)(WshB + (((kq * 16 + si) * 4 + nt) << 6) + lane * 2);
                        mma_f16(acc[0][nt][0], acc[0][nt][1], acc[0][nt][2], acc[0][nt][3],
                                b[cur][s][0].x, b[cur][s][0].y, b[cur][s][0].z, b[cur][s][0].w, w.x, w.y);
                        mma_f16(acc[1][nt][0], acc[1][nt][1], acc[1][nt][2], acc[1][nt][3],
                                b[cur][s][1].x, b[cur][s][1].y, b[cur][s][1].z, b[cur][s][1].w, w.x, w.y);
                    }
                }
            }
            #pragma unroll
            for (int mt = 0; mt < 2; mt++)
                #pragma unroll
                for (int nt = 0; nt < 4; nt++) {
                    int row = kq * 32 + mt * 16 + g;
                    RshB[row * RPK + nt * 4 + t]       = pack_h2(acc[mt][nt][0], acc[mt][nt][1]);
                    RshB[(row + 8) * RPK + nt * 4 + t] = pack_h2(acc[mt][nt][2], acc[mt][nt][3]);
                }
            barn(4, 256);

            {
                float s0 = bias1[0], s1 = bias1[1], s2 = bias1[2], s3 = bias1[3];
                const int sel = ej & 1;
                #pragma unroll
                for (int kk = 0; kk < 8; kk++) {
                    const unsigned* rp = RshB + (kk * 32 + eb) * RPK + (ej >> 1);
                    #pragma unroll
                    for (int q = 0; q < 4; q++) {
                        __half2 hv = *(const __half2*)&rp[q * 4];
                        float2 f = __half22float2(hv);
                        float v = sel ? f.y : f.x;
                        if (q == 0) s0 += v; else if (q == 1) s1 += v;
                        else if (q == 2) s2 += v; else s3 += v;
                    }
                }
                float iv = sigm(s0), fv = sigm(s1), gv = fast_tanh(s2), ov = sigm(s3);
                c1_state = fv * c1_state + iv * gv;
                float h1val = ov * fast_tanh(c1_state);
                unsigned hb = (unsigned)__half_as_ushort(__float2half_rn(h1val));
                unsigned ob = __shfl_xor_sync(0xffffffffu, hb, 1);
                if ((ej & 1) == 0)
                    g_h1H[(r + 1) & 1][foff] = (hb & 0xffffu) | (ob << 16);
                float h0_res = __half2float(hbuf[((r + 1) & 1) * 256 + cix]);  // h0[r-1]
                outseq[((size_t)eb * T_ + (r - 1)) * H_ + hcol] = h1val + h0_res;
            }
            barn(5, 256);
            if (tid == 0) flag_release(g_f1);     // f1 phase r
        }
    }
}

// ---------------- launch ----------------
extern "C" void kernel_launch(void* const* d_in, const int* in_sizes, int n_in,
                              void* d_out, int out_size) {
    const float* x    = (const float*)d_in[0];
    const float* Wih0 = (const float*)d_in[1];
    const float* Whh0 = (const float*)d_in[2];
    const float* bih0 = (const float*)d_in[3];
    const float* bhh0 = (const float*)d_in[4];
    const float* Wih1 = (const float*)d_in[5];
    const float* Whh1 = (const float*)d_in[6];
    const float* bih1 = (const float*)d_in[7];
    const float* bhh1 = (const float*)d_in[8];
    float* out = (float*)d_out;

    cudaFuncSetAttribute(lstm_fused_kernel,
                         cudaFuncAttributeMaxDynamicSharedMemorySize, FUSED_SMEM);

    void* p;
    cudaGetSymbolAddress(&p, g_xg);  float* xg = (float*)p;
    cudaGetSymbolAddress(&p, g_f0);  unsigned* f0 = (unsigned*)p;
    cudaGetSymbolAddress(&p, g_f1);  unsigned* f1 = (unsigned*)p;

    dim3 gg(32, 128);

    cudaMemsetAsync(f0, 0, sizeof(unsigned) * NCNT * CSTR);
    cudaMemsetAsync(f1, 0, sizeof(unsigned) * NCNT * CSTR);
    gemm_xg_kernel<<<gg, 256>>>(x, Wih0, bih0, bhh0, xg);
    lstm_fused_kernel<<<NBLK, NTHR, FUSED_SMEM>>>(xg, Whh0, Wih1, Whh1, bih1, bhh1, out);
}

// round 14
// speedup vs baseline: 2.2955x; 1.0231x over previous
#include <cuda_runtime.h>
#include <cuda_fp16.h>
#include <cstdint>

#define B_  32
#define T_  512
#define H_  1024
#define G4_ 4096
#define M_  (B_ * T_)   // 16384
#define NBLK 128
#define NTHR 512
#define CSTR 64          // counter stride in u32 (256 B)
#define NC0  8           // f0 counters: stripe = bid>>4 (16 blocks each)
#define NC1  16          // f1 counters: stripe = bid&15 (8 blocks each)

// ---------------- static device scratch ----------------
__device__ float g_xg[(size_t)M_ * G4_];     // layer-0 gate preactivations (from GEMM0)
__device__ unsigned g_h0H[4][16384];         // frag-permuted fp16 h0, depth-4 (slot r&3)
__device__ unsigned g_h1H[2][16384];         // h1, parity
__device__ unsigned g_f0[NC0 * CSTR];        // h0-publish flags (per-warp release: +8/block/round)
__device__ unsigned g_f1[NC1 * CSTR];        // L1-done flags   (per-warp release: +8/block/round)

// ---------------- helpers ----------------
__device__ __forceinline__ void mma_f16(float& c0, float& c1, float& c2, float& c3,
                                        uint32_t a0, uint32_t a1, uint32_t a2, uint32_t a3,
                                        uint32_t b0, uint32_t b1) {
    asm volatile(
        "mma.sync.aligned.m16n8k16.row.col.f32.f16.f16.f32 "
        "{%0,%1,%2,%3},{%4,%5,%6,%7},{%8,%9},{%0,%1,%2,%3};"
        : "+f"(c0), "+f"(c1), "+f"(c2), "+f"(c3)
        : "r"(a0), "r"(a1), "r"(a2), "r"(a3), "r"(b0), "r"(b1));
}

__device__ __forceinline__ float tanha(float x) {
    float y;
    asm("tanh.approx.f32 %0, %1;" : "=f"(y) : "f"(x));
    return y;
}
__device__ __forceinline__ float sigm(float x) {
    return fmaf(tanha(0.5f * x), 0.5f, 0.5f);
}

__device__ __forceinline__ unsigned pack_h2(float a, float b) {
    __half2 h = __floats2half2_rn(a, b);
    return *(unsigned*)&h;
}

__device__ __forceinline__ void barn(int id, int cnt) {
    asm volatile("bar.sync %0, %1;" :: "r"(id), "r"(cnt) : "memory");
}

__device__ __forceinline__ void flag_release_idx(unsigned* base, int idx) {
    asm volatile("red.release.gpu.global.add.u32 [%0], 1;"
                 :: "l"(&base[idx * CSTR]) : "memory");
}

__device__ __forceinline__ void flag_poll(const unsigned* base, int idx, unsigned target) {
    const unsigned* cp = &base[idx * CSTR];
    unsigned v;
    asm volatile("ld.acquire.gpu.global.u32 %0, [%1];" : "=r"(v) : "l"(cp) : "memory");
    while (v < target) {
        __nanosleep(64);
        asm volatile("ld.acquire.gpu.global.u32 %0, [%1];" : "=r"(v) : "l"(cp) : "memory");
    }
}

// ---------------- big GEMM (fp16 mma): C[M,4096] = A[M,1024]*W^T + bias ----------------
#define GS_ 12

__global__ __launch_bounds__(256, 2)
void gemm_xg_kernel(const float* __restrict__ A,
                    const float* __restrict__ W,
                    const float* __restrict__ b0,
                    const float* __restrict__ b1,
                    float* __restrict__ C)
{
    __shared__ unsigned Ash[128 * GS_];
    __shared__ unsigned Bsh[128 * GS_];

    const int tid  = threadIdx.x;
    const int wid  = tid >> 5, lane = tid & 31;
    const int g    = lane >> 2, t = lane & 3;
    const int wm   = wid & 1, wn = wid >> 1;
    const int cm   = blockIdx.y * 128;
    const int cn   = blockIdx.x * 128;

    float acc[4][4][4];
    #pragma unroll
    for (int i = 0; i < 4; i++)
        #pragma unroll
        for (int j = 0; j < 4; j++)
            #pragma unroll
            for (int q = 0; q < 4; q++) acc[i][j][q] = 0.0f;

    const int r0 = tid >> 1;
    const int q0 = tid & 1;

    const float* Ag = A + (size_t)(cm + r0) * 1024 + 8 * q0;
    const float* Bg = W + (size_t)(cn + r0) * 1024 + 8 * q0;

    float4 av0 = *(const float4*)(Ag);
    float4 av1 = *(const float4*)(Ag + 4);
    float4 bv0 = *(const float4*)(Bg);
    float4 bv1 = *(const float4*)(Bg + 4);

    for (int kk = 0; kk < 1024; kk += 16) {
        __syncthreads();
        {
            uint4 pa, pb;
            pa.x = pack_h2(av0.x, av0.y); pa.y = pack_h2(av0.z, av0.w);
            pa.z = pack_h2(av1.x, av1.y); pa.w = pack_h2(av1.z, av1.w);
            pb.x = pack_h2(bv0.x, bv0.y); pb.y = pack_h2(bv0.z, bv0.w);
            pb.z = pack_h2(bv1.x, bv1.y); pb.w = pack_h2(bv1.z, bv1.w);
            *(uint4*)(Ash + r0 * GS_ + 4 * q0) = pa;
            *(uint4*)(Bsh + r0 * GS_ + 4 * q0) = pb;
        }
        __syncthreads();

        if (kk + 16 < 1024) {
            av0 = *(const float4*)(Ag + kk + 16);
            av1 = *(const float4*)(Ag + kk + 20);
            bv0 = *(const float4*)(Bg + kk + 16);
            bv1 = *(const float4*)(Bg + kk + 20);
        }

        uint32_t af[4][4];
        uint32_t bf[4][2];
        #pragma unroll
        for (int mt = 0; mt < 4; mt++) {
            int rb = wm * 64 + mt * 16;
            af[mt][0] = Ash[(rb + g)     * GS_ + t];
            af[mt][1] = Ash[(rb + g + 8) * GS_ + t];
            af[mt][2] = Ash[(rb + g)     * GS_ + t + 4];
            af[mt][3] = Ash[(rb + g + 8) * GS_ + t + 4];
        }
        #pragma unroll
        for (int nt = 0; nt < 4; nt++) {
            int nb = wn * 32 + nt * 8 + g;
            bf[nt][0] = Bsh[nb * GS_ + t];
            bf[nt][1] = Bsh[nb * GS_ + t + 4];
        }
        #pragma unroll
        for (int mt = 0; mt < 4; mt++)
            #pragma unroll
            for (int nt = 0; nt < 4; nt++)
                mma_f16(acc[mt][nt][0], acc[mt][nt][1], acc[mt][nt][2], acc[mt][nt][3],
                        af[mt][0], af[mt][1], af[mt][2], af[mt][3],
                        bf[nt][0], bf[nt][1]);
    }

    #pragma unroll
    for (int mt = 0; mt < 4; mt++) {
        #pragma unroll
        for (int nt = 0; nt < 4; nt++) {
            int m = cm + wm * 64 + mt * 16 + g;
            int n = cn + wn * 32 + nt * 8 + 2 * t;
            float bs0 = b0[n] + b1[n];
            float bs1 = b0[n + 1] + b1[n + 1];
            float2 v0 = make_float2(acc[mt][nt][0] + bs0, acc[mt][nt][1] + bs1);
            float2 v1 = make_float2(acc[mt][nt][2] + bs0, acc[mt][nt][3] + bs1);
            *(float2*)(C + (size_t)m * G4_ + n) = v0;
            *(float2*)(C + (size_t)(m + 8) * G4_ + n) = v1;
        }
    }
}

// ---------------- fused two-layer scan, per-warp producer-aligned dataflow ----------------
// Warps 8-15 = layer-0 (critical path); warps 0-7 = layer-1.
// f0 counter k covers producers (blocks) [16k,16k+16); L0 warp kq polls ONLY counter kq
// before its LDG+mma (chunks [8kq,8kq+8) come exactly from that stripe).
// Per-warp release (syncwarp + red.release) removes publish-side block barrier.
// h0 depth 4 + L1 lag <= 2 (f1 >= r-2, checked just before publish, off the load path).
#define WA_  16384
#define WB_  32768
#define RPK  17
#define RPKS (8 * 32 * RPK)
#define FUSED_SMEM ((WA_ + WB_ + 2 * RPKS) * 4)   // 231424 B (hbuf lives in RPK holes)

__global__ __launch_bounds__(NTHR, 1)
void lstm_fused_kernel(const float* __restrict__ xg,
                       const float* __restrict__ Whh0,
                       const float* __restrict__ Wih1,
                       const float* __restrict__ Whh1,
                       const float* __restrict__ bih1,
                       const float* __restrict__ bhh1,
                       float* __restrict__ outseq)
{
    extern __shared__ unsigned smu[];
    unsigned* WshA = smu;
    unsigned* WshB = smu + WA_;
    unsigned* RshA = smu + WA_ + WB_;
    unsigned* RshB = RshA + RPKS;

    const int tid  = threadIdx.x;
    const int bid  = blockIdx.x;
    const int wid  = tid >> 5, lane = tid & 31;
    const int g    = lane >> 2, t = lane & 3;

    // ---- fill Whh0 frags ----
    for (int e = tid; e < WA_; e += NTHR) {
        int rr = e & 1;
        int ln = (e >> 1) & 31;
        int nt = (e >> 6) & 3;
        int si = (e >> 8) & 7;
        int kq = e >> 11;
        int n8 = ln >> 2, tt = ln & 3;
        int row = nt * 1024 + bid * 8 + n8;
        int k0  = kq * 128 + si * 16 + 2 * tt + rr * 8;
        WshA[e] = pack_h2(Whh0[(size_t)row * 1024 + k0],
                          Whh0[(size_t)row * 1024 + k0 + 1]);
    }
    // ---- fill [Wih1|Whh1] frags (K=2048) ----
    for (int e = tid; e < WB_; e += NTHR) {
        int rr = e & 1;
        int ln = (e >> 1) & 31;
        int nt = (e >> 6) & 3;
        int si = (e >> 8) & 15;
        int kq = e >> 12;
        int n8 = ln >> 2, tt = ln & 3;
        int row = nt * 1024 + bid * 8 + n8;
        int kg  = kq * 256 + si * 16 + 2 * tt + rr * 8;
        const float* src = (kg < 1024) ? (Wih1 + (size_t)row * 1024 + kg)
                                       : (Whh1 + (size_t)row * 1024 + (kg - 1024));
        WshB[e] = pack_h2(src[0], src[1]);
    }

    const int cix  = tid & 255;
    const int eb   = cix >> 3;
    const int ej   = cix & 7;
    const int hcol = bid * 8 + ej;
    const int c_   = bid >> 1;
    const int fmt  = eb >> 4;
    const int ridx = (bid & 1) * 2 + ((eb >> 3) & 1);
    const int foff = (((c_ * 2 + fmt) * 32) + (eb & 7) * 4 + (ej >> 1)) * 4 + ridx;

    // hbuf slot d (0..3) for this cix lives in the RPK padding holes (col 16):
    //   base buffer = (d<2 ? RshA : RshB), row = (d&1)*128 + (cix>>1), half sel = cix&1
    const int hb_row = (cix >> 1) * RPK + 16;
    const int hb_sel = cix & 1;

    float c0_state = 0.0f, c1_state = 0.0f;
    float bias1[4];
    if (tid >= 256) {                           // L0 half
        if ((ej & 1) == 0) g_h0H[3][foff] = 0u; // h0[-1] -> slot 3
    } else {                                    // L1 half
        #pragma unroll
        for (int q = 0; q < 4; q++)
            bias1[q] = bih1[q * 1024 + hcol] + bhh1[q * 1024 + hcol];
        if ((ej & 1) == 0) g_h1H[1][foff] = 0u; // h1[-1] -> parity 1
    }

    // init publish: every L0 warp releases once (covers both halves' zeros via bar)
    __syncthreads();
    if (tid >= 256 && lane == 0) flag_release_idx(g_f0, bid >> 4);

    if (tid >= 256) {
        // ================= layer-0 chain (warps 8-15) =================
        const int kq = wid - 8;
        for (int r = 0; r < T_; r++) {
            // prefetch xg (independent of flags)
            const float* xp = xg + ((size_t)eb * T_ + r) * G4_ + hcol;
            float xv0 = __ldcs(xp);
            float xv1 = __ldcs(xp + 1024);
            float xv2 = __ldcs(xp + 2048);
            float xv3 = __ldcs(xp + 3072);

            // per-warp wait: only MY 16 producers (stripe kq) must have published h0[r-1]
            if (lane == 0) flag_poll(g_f0, kq, (unsigned)(r + 1) * 128u);
            __syncwarp();

            float acc[2][4][4];
            #pragma unroll
            for (int mt = 0; mt < 2; mt++)
                #pragma unroll
                for (int nt = 0; nt < 4; nt++)
                    #pragma unroll
                    for (int q = 0; q < 4; q++) acc[mt][nt][q] = 0.0f;

            const uint4* hA = (const uint4*)g_h0H[(r + 3) & 3];   // h0[r-1]
            uint4 a[2][4][2];
            #pragma unroll
            for (int h2 = 0; h2 < 2; h2++)
                #pragma unroll
                for (int s = 0; s < 4; s++) {
                    int c = kq * 8 + h2 * 4 + s;
                    a[h2][s][0] = __ldcg(hA + (c * 2 + 0) * 32 + lane);
                    a[h2][s][1] = __ldcg(hA + (c * 2 + 1) * 32 + lane);
                }
            #pragma unroll
            for (int h2 = 0; h2 < 2; h2++)
                #pragma unroll
                for (int s = 0; s < 4; s++) {
                    int si = h2 * 4 + s;
                    #pragma unroll
                    for (int nt = 0; nt < 4; nt++) {
                        uint2 w = *(const uint2*)(WshA + (((kq * 8 + si) * 4 + nt) << 6) + lane * 2);
                        mma_f16(acc[0][nt][0], acc[0][nt][1], acc[0][nt][2], acc[0][nt][3],
                                a[h2][s][0].x, a[h2][s][0].y, a[h2][s][0].z, a[h2][s][0].w, w.x, w.y);
                        mma_f16(acc[1][nt][0], acc[1][nt][1], acc[1][nt][2], acc[1][nt][3],
                                a[h2][s][1].x, a[h2][s][1].y, a[h2][s][1].z, a[h2][s][1].w, w.x, w.y);
                    }
                }

            barn(2, 256);                      // RshA free (prev round's reduce done)
            #pragma unroll
            for (int mt = 0; mt < 2; mt++)
                #pragma unroll
                for (int nt = 0; nt < 4; nt++) {
                    int row = kq * 32 + mt * 16 + g;
                    RshA[row * RPK + nt * 4 + t]       = pack_h2(acc[mt][nt][0], acc[mt][nt][1]);
                    RshA[(row + 8) * RPK + nt * 4 + t] = pack_h2(acc[mt][nt][2], acc[mt][nt][3]);
                }
            barn(1, 256);                      // partials ready

            float s0 = xv0, s1 = xv1, s2 = xv2, s3 = xv3;
            const int sel = ej & 1;
            #pragma unroll
            for (int kk = 0; kk < 8; kk++) {
                const unsigned* rp = RshA + (kk * 32 + eb) * RPK + (ej >> 1);
                #pragma unroll
                for (int q = 0; q < 4; q++) {
                    __half2 hv = *(const __half2*)&rp[q * 4];
                    float2 f = __half22float2(hv);
                    float v = sel ? f.y : f.x;
                    if (q == 0) s0 += v; else if (q == 1) s1 += v;
                    else if (q == 2) s2 += v; else s3 += v;
                }
            }
            float iv = sigm(s0), fv = sigm(s1), gv = tanha(s2), ov = sigm(s3);
            c0_state = fv * c0_state + iv * gv;
            float hval = ov * tanha(c0_state);

            // anti-dependency: before overwriting slot r&3 / hbuf, all L1 rounds <= r-2 done
            if (r >= 3 && lane < NC1)
                flag_poll(g_f1, lane, (unsigned)(r - 2) * 64u);
            __syncwarp();

            // publish h0[r] (frag-permuted fp16) + residual into hbuf hole
            unsigned hb = (unsigned)__half_as_ushort(__float2half_rn(hval));
            unsigned ob = __shfl_xor_sync(0xffffffffu, hb, 1);
            int d = r & 3;
            if ((ej & 1) == 0)
                g_h0H[d][foff] = (hb & 0xffffu) | (ob << 16);
            {
                unsigned* hrow = (d < 2 ? RshA : RshB) + (d & 1) * 128 * RPK + hb_row;
                ((__half*)hrow)[hb_sel] = __float2half_rn(hval);
            }
            __syncwarp();
            if (lane == 0) flag_release_idx(g_f0, bid >> 4);
        }
    } else {
        // ================= layer-1 chain (warps 0-7) =================
        const int kq = wid;
        for (int r = 1; r <= T_; r++) {
            // per-warp waits
            if (kq < 4) {
                if (lane < 2) flag_poll(g_f0, 2 * kq + lane, (unsigned)(r + 1) * 128u);
            } else {
                if (r == 1) { if (lane < NC0) flag_poll(g_f0, lane, 2u * 128u); }
                else        { if (lane < NC1) flag_poll(g_f1, lane, (unsigned)(r - 1) * 64u); }
            }
            __syncwarp();

            float acc[2][4][4];
            #pragma unroll
            for (int mt = 0; mt < 2; mt++)
                #pragma unroll
                for (int nt = 0; nt < 4; nt++)
                    #pragma unroll
                    for (int q = 0; q < 4; q++) acc[mt][nt][q] = 0.0f;

            const uint4* baseA;
            int cb;
            if (kq < 4) { baseA = (const uint4*)g_h0H[(r + 3) & 3]; cb = kq * 16; }       // h0[r-1]
            else        { baseA = (const uint4*)g_h1H[r & 1];       cb = (kq - 4) * 16; } // h1[r-2]

            uint4 b[2][2][2];
            #pragma unroll
            for (int s = 0; s < 2; s++) {
                int c = cb + s;
                b[0][s][0] = __ldcg(baseA + (c * 2 + 0) * 32 + lane);
                b[0][s][1] = __ldcg(baseA + (c * 2 + 1) * 32 + lane);
            }
            #pragma unroll
            for (int wv = 0; wv < 8; wv++) {
                int cur = wv & 1;
                if (wv < 7) {
                    #pragma unroll
                    for (int s = 0; s < 2; s++) {
                        int c = cb + (wv + 1) * 2 + s;
                        b[1 - cur][s][0] = __ldcg(baseA + (c * 2 + 0) * 32 + lane);
                        b[1 - cur][s][1] = __ldcg(baseA + (c * 2 + 1) * 32 + lane);
                    }
                }
                #pragma unroll
                for (int s = 0; s < 2; s++) {
                    int si = wv * 2 + s;
                    #pragma unroll
                    for (int nt = 0; nt < 4; nt++) {
                        uint2 w = *(const uint2*)(WshB + (((kq * 16 + si) * 4 + nt) << 6) + lane * 2);
                        mma_f16(acc[0][nt][0], acc[0][nt][1], acc[0][nt][2], acc[0][nt][3],
                                b[cur][s][0].x, b[cur][s][0].y, b[cur][s][0].z, b[cur][s][0].w, w.x, w.y);
                        mma_f16(acc[1][nt][0], acc[1][nt][1], acc[1][nt][2], acc[1][nt][3],
                                b[cur][s][1].x, b[cur][s][1].y, b[cur][s][1].z, b[cur][s][1].w, w.x, w.y);
                    }
                }
            }

            barn(4, 256);                      // RshB data cols free
            #pragma unroll
            for (int mt = 0; mt < 2; mt++)
                #pragma unroll
                for (int nt = 0; nt < 4; nt++) {
                    int row = kq * 32 + mt * 16 + g;
                    RshB[row * RPK + nt * 4 + t]       = pack_h2(acc[mt][nt][0], acc[mt][nt][1]);
                    RshB[(row + 8) * RPK + nt * 4 + t] = pack_h2(acc[mt][nt][2], acc[mt][nt][3]);
                }
            barn(3, 256);                      // partials ready

            float s0 = bias1[0], s1 = bias1[1], s2 = bias1[2], s3 = bias1[3];
            const int sel = ej & 1;
            #pragma unroll
            for (int kk = 0; kk < 8; kk++) {
                const unsigned* rp = RshB + (kk * 32 + eb) * RPK + (ej >> 1);
                #pragma unroll
                for (int q = 0; q < 4; q++) {
                    __half2 hv = *(const __half2*)&rp[q * 4];
                    float2 f = __half22float2(hv);
                    float v = sel ? f.y : f.x;
                    if (q == 0) s0 += v; else if (q == 1) s1 += v;
                    else if (q == 2) s2 += v; else s3 += v;
                }
            }
            float iv = sigm(s0), fv = sigm(s1), gv = tanha(s2), ov = sigm(s3);
            c1_state = fv * c1_state + iv * gv;
            float h1val = ov * tanha(c1_state);
            unsigned hb = (unsigned)__half_as_ushort(__float2half_rn(h1val));
            unsigned ob = __shfl_xor_sync(0xffffffffu, hb, 1);
            if ((ej & 1) == 0)
                g_h1H[(r + 1) & 1][foff] = (hb & 0xffffu) | (ob << 16);
            // residual from hbuf hole, slot (r-1)&3
            {
                int d = (r - 1) & 3;
                const unsigned* hrow = (d < 2 ? RshA : RshB) + (d & 1) * 128 * RPK + hb_row;
                float h0_res = __half2float(((const __half*)hrow)[hb_sel]);
                outseq[((size_t)eb * T_ + (r - 1)) * H_ + hcol] = h1val + h0_res;
            }
            __syncwarp();
            if (lane == 0) flag_release_idx(g_f1, bid & 15);
        }
    }
}

// ---------------- launch ----------------
extern "C" void kernel_launch(void* const* d_in, const int* in_sizes, int n_in,
                              void* d_out, int out_size) {
    const float* x    = (const float*)d_in[0];
    const float* Wih0 = (const float*)d_in[1];
    const float* Whh0 = (const float*)d_in[2];
    const float* bih0 = (const float*)d_in[3];
    const float* bhh0 = (const float*)d_in[4];
    const float* Wih1 = (const float*)d_in[5];
    const float* Whh1 = (const float*)d_in[6];
    const float* bih1 = (const float*)d_in[7];
    const float* bhh1 = (const float*)d_in[8];
    float* out = (float*)d_out;

    cudaFuncSetAttribute(lstm_fused_kernel,
                         cudaFuncAttributeMaxDynamicSharedMemorySize, FUSED_SMEM);

    void* p;
    cudaGetSymbolAddress(&p, g_xg);  float* xg = (float*)p;
    cudaGetSymbolAddress(&p, g_f0);  unsigned* f0 = (unsigned*)p;
    cudaGetSymbolAddress(&p, g_f1);  unsigned* f1 = (unsigned*)p;

    dim3 gg(32, 128);

    cudaMemsetAsync(f0, 0, sizeof(unsigned) * NC0 * CSTR);
    cudaMemsetAsync(f1, 0, sizeof(unsigned) * NC1 * CSTR);
    gemm_xg_kernel<<<gg, 256>>>(x, Wih0, bih0, bhh0, xg);
    lstm_fused_kernel<<<NBLK, NTHR, FUSED_SMEM>>>(xg, Whh0, Wih1, Whh1, bih1, bhh1, out);
}